// round 2
// baseline (speedup 1.0000x reference)
#include <cuda_runtime.h>
#include <cuda_bf16.h>

// Problem constants (fixed by the dataset)
#define NN 100000
#define NE 1600000
#define SCAN_B 1024
#define NB_SCAN ((NN + SCAN_B - 1) / SCAN_B)   // 98

// ---------------- scratch (device globals; no allocation allowed) -------------
__device__ int   g_flag64;           // 1 if edge_index buffer is int64
__device__ int   g_src[NE];
__device__ int   g_dst[NE];
__device__ int   g_cnt[NN];
__device__ int   g_fill[NN];
__device__ int   g_ptr[NN + 1];
__device__ int   g_bsum[128];
__device__ int   g_csrc[NE];
__device__ float g_csw[NE];
__device__ float g_sumw[NN];
__device__ float g_loop[NN];
__device__ float g_xl[(size_t)NN * 128];
__device__ float g_h[(size_t)NN * 128];
__device__ float g_asrc[NN];
__device__ float g_adst[NN];
__device__ float g_c[4];

// ---------------- dtype probe + conversion ------------------------------------
// Reads only the first 4096 entries interpreted as int64 — that's 32 KB,
// within the buffer under either dtype (int32 buffer = 8E bytes = 12.8 MB).
__global__ void k_probe(const void* __restrict__ ei_raw, int* __restrict__ flag) {
    __shared__ int bad;
    if (threadIdx.x == 0) bad = 0;
    __syncthreads();
    const long long* p = (const long long*)ei_raw;
    for (int i = threadIdx.x; i < 4096; i += blockDim.x) {
        long long v = p[i];
        if (v < 0 || v >= (long long)NN) bad = 1;
    }
    __syncthreads();
    if (threadIdx.x == 0) *flag = bad ? 0 : 1;
}

__global__ void k_convert(const void* __restrict__ ei_raw, const int* __restrict__ flag,
                          int* __restrict__ src, int* __restrict__ dst, int E) {
    int e = blockIdx.x * blockDim.x + threadIdx.x;
    if (e >= E) return;
    if (*flag) {
        const long long* p = (const long long*)ei_raw;
        src[e] = (int)p[e];
        dst[e] = (int)p[E + e];
    } else {
        const int* p = (const int*)ei_raw;
        src[e] = p[e];
        dst[e] = p[E + e];
    }
}

// ---------------- CSR build ---------------------------------------------------
__global__ void k_hist(const int* __restrict__ dst, int* __restrict__ cnt, int E) {
    int e = blockIdx.x * blockDim.x + threadIdx.x;
    if (e < E) atomicAdd(&cnt[dst[e]], 1);
}

__global__ void k_scan1(const int* __restrict__ cnt, int* __restrict__ ptr,
                        int* __restrict__ bsum, int n) {
    __shared__ int sm[SCAN_B];
    int i = blockIdx.x * SCAN_B + threadIdx.x;
    int v = (i < n) ? cnt[i] : 0;
    sm[threadIdx.x] = v;
    __syncthreads();
    for (int off = 1; off < SCAN_B; off <<= 1) {
        int t = (threadIdx.x >= off) ? sm[threadIdx.x - off] : 0;
        __syncthreads();
        sm[threadIdx.x] += t;
        __syncthreads();
    }
    if (i < n) ptr[i + 1] = sm[threadIdx.x];
    if (threadIdx.x == SCAN_B - 1) bsum[blockIdx.x] = sm[SCAN_B - 1];
    if (i == 0) ptr[0] = 0;
}

__global__ void k_scan2(int* __restrict__ bsum, int nb) {
    __shared__ int sm[128];
    int t = threadIdx.x;
    sm[t] = (t < nb) ? bsum[t] : 0;
    __syncthreads();
    if (t == 0) {
        int run = 0;
        for (int i = 0; i < nb; i++) { int v = sm[i]; sm[i] = run; run += v; }
    }
    __syncthreads();
    if (t < nb) bsum[t] = sm[t];
}

__global__ void k_scan3(int* __restrict__ ptr, const int* __restrict__ bsum, int n) {
    int i = blockIdx.x * SCAN_B + threadIdx.x;
    if (i < n) ptr[i + 1] += bsum[blockIdx.x];
}

__global__ void k_scatter(const int* __restrict__ src, const int* __restrict__ dst,
                          const float* __restrict__ ew,
                          const int* __restrict__ ptr, int* __restrict__ fill,
                          int* __restrict__ csrc, float* __restrict__ csw,
                          float* __restrict__ sumw, int E) {
    int e = blockIdx.x * blockDim.x + threadIdx.x;
    if (e >= E) return;
    int s = src[e];
    int d = dst[e];
    float w = ew[e];
    int pos = ptr[d] + atomicAdd(&fill[d], 1);
    csrc[pos] = s;
    csw[pos] = w;
    atomicAdd(&sumw[d], w);
}

__global__ void k_loopattr(const int* __restrict__ cnt, const float* __restrict__ sumw,
                           float* __restrict__ la, int n) {
    int i = blockIdx.x * blockDim.x + threadIdx.x;
    if (i < n) {
        int c = cnt[i];
        la[i] = (c > 0) ? (sumw[i] / (float)c) : 0.0f;
    }
}

// small dot: c = dot(a,b) over len elements
__global__ void k_dot(const float* __restrict__ a, const float* __restrict__ b,
                      float* __restrict__ out, int len) {
    __shared__ float sm[128];
    int t = threadIdx.x;
    float p = 0.f;
    for (int i = t; i < len; i += 128) p += a[i] * b[i];
    sm[t] = p;
    __syncthreads();
    for (int off = 64; off; off >>= 1) {
        if (t < off) sm[t] += sm[t + off];
        __syncthreads();
    }
    if (t == 0) *out = sm[0];
}

// ---------------- GEMM: Y[n,NOUT] = X[n,128] @ W[128,NOUT], fused a_src/a_dst --
template <int NOUT>
__global__ void k_gemm(const float* __restrict__ X, const float* __restrict__ W,
                       const float* __restrict__ a_s, const float* __restrict__ a_d,
                       float* __restrict__ Y, float* __restrict__ asrc,
                       float* __restrict__ adst, int n) {
    constexpr int CPL = NOUT / 32;   // cols per lane (4 or 2)
    extern __shared__ float smem[];
    float* ws = smem;                 // [128 * NOUT]
    float* xs = smem + 128 * NOUT;    // [64 * 128]

    int tid = threadIdx.x;
    int base = blockIdx.x * 64;

    // load W
    for (int i = tid; i < 128 * NOUT / 4; i += 256)
        ((float4*)ws)[i] = ((const float4*)W)[i];
    // load X tile (zero-pad beyond n)
    for (int i = tid; i < 64 * 32; i += 256) {
        int r = i >> 5, c4 = i & 31;
        int row = base + r;
        float4 t = make_float4(0.f, 0.f, 0.f, 0.f);
        if (row < n) t = ((const float4*)(X + (size_t)row * 128))[c4];
        ((float4*)(xs + r * 128))[c4] = t;
    }
    __syncthreads();

    int warp = tid >> 5, lane = tid & 31;
    float acc[8][CPL];
#pragma unroll
    for (int r = 0; r < 8; r++)
#pragma unroll
        for (int j = 0; j < CPL; j++) acc[r][j] = 0.f;

    for (int k = 0; k < 128; k++) {
        if constexpr (CPL == 4) {
            float4 wv = ((const float4*)(ws + k * NOUT))[lane];
#pragma unroll
            for (int r = 0; r < 8; r++) {
                float xv = xs[(warp * 8 + r) * 128 + k];
                acc[r][0] += xv * wv.x;
                acc[r][1] += xv * wv.y;
                acc[r][2] += xv * wv.z;
                acc[r][3] += xv * wv.w;
            }
        } else {
            float2 wv = ((const float2*)(ws + k * NOUT))[lane];
#pragma unroll
            for (int r = 0; r < 8; r++) {
                float xv = xs[(warp * 8 + r) * 128 + k];
                acc[r][0] += xv * wv.x;
                acc[r][1] += xv * wv.y;
            }
        }
    }

    // attention vectors per-lane chunks
    float av[CPL], dv[CPL];
#pragma unroll
    for (int j = 0; j < CPL; j++) {
        av[j] = a_s[lane * CPL + j];
        dv[j] = a_d[lane * CPL + j];
    }

#pragma unroll
    for (int r = 0; r < 8; r++) {
        int row = base + warp * 8 + r;
        float pa = 0.f, pd = 0.f;
#pragma unroll
        for (int j = 0; j < CPL; j++) {
            pa += acc[r][j] * av[j];
            pd += acc[r][j] * dv[j];
        }
#pragma unroll
        for (int off = 16; off; off >>= 1) {
            pa += __shfl_xor_sync(0xffffffffu, pa, off);
            pd += __shfl_xor_sync(0xffffffffu, pd, off);
        }
        if (row < n) {
            if constexpr (CPL == 4) {
                float4 o = make_float4(acc[r][0], acc[r][1], acc[r][2], acc[r][3]);
                ((float4*)(Y + (size_t)row * NOUT))[lane] = o;
            } else {
                float2 o = make_float2(acc[r][0], acc[r][1]);
                ((float2*)(Y + (size_t)row * NOUT))[lane] = o;
            }
            if (lane == 0) { asrc[row] = pa; adst[row] = pd; }
        }
    }
}

// ---------------- aggregation: per-dst softmax + weighted gather --------------
__device__ __forceinline__ float lrelu(float a) { return a > 0.f ? a : 0.2f * a; }

template <int F, bool EDGE, bool RELU>
__global__ void k_aggregate(const float* __restrict__ xl, const float* __restrict__ asrc,
                            const float* __restrict__ adst, const int* __restrict__ ptr,
                            const int* __restrict__ csrc, const float* __restrict__ csw,
                            const float* __restrict__ la, const float* __restrict__ cvec,
                            int cidx, const float* __restrict__ bias,
                            float* __restrict__ out, int n) {
    constexpr int CPL = F / 32;   // 4 for F=128, 2 for F=64
    int wid = (blockIdx.x * blockDim.x + threadIdx.x) >> 5;
    int lane = threadIdx.x & 31;
    if (wid >= n) return;
    int v = wid;

    float c = EDGE ? cvec[cidx] : 0.f;
    float adv = adst[v];

    // self loop
    float a0 = asrc[v] + adv;
    if (EDGE) a0 += la[v] * c;
    a0 = lrelu(a0);
    float m = a0, den = 1.0f;

    float acc[CPL];
    {
        const float* row = xl + (size_t)v * F;
        if constexpr (CPL == 4) {
            float4 t = ((const float4*)row)[lane];
            acc[0] = t.x; acc[1] = t.y; acc[2] = t.z; acc[3] = t.w;
        } else {
            float2 t = ((const float2*)row)[lane];
            acc[0] = t.x; acc[1] = t.y;
        }
    }

    int rs = ptr[v], re = ptr[v + 1];
    for (int b = rs; b < re; b += 32) {
        int e = b + lane;
        float al = 0.f;
        int sIdx = 0;
        if (e < re) {
            sIdx = csrc[e];
            float a = asrc[sIdx] + adv;
            if (EDGE) a += csw[e] * c;
            al = lrelu(a);
        }
        int cnt = min(32, re - b);
        for (int j = 0; j < cnt; j++) {
            float a = __shfl_sync(0xffffffffu, al, j);
            int s = __shfl_sync(0xffffffffu, sIdx, j);
            float w;
            if (a > m) {           // warp-uniform branch
                float r = __expf(m - a);
                den *= r;
#pragma unroll
                for (int i = 0; i < CPL; i++) acc[i] *= r;
                m = a;
                w = 1.0f;
            } else {
                w = __expf(a - m);
            }
            den += w;
            const float* srow = xl + (size_t)s * F;
            if constexpr (CPL == 4) {
                float4 t = ((const float4*)srow)[lane];
                acc[0] += w * t.x; acc[1] += w * t.y;
                acc[2] += w * t.z; acc[3] += w * t.w;
            } else {
                float2 t = ((const float2*)srow)[lane];
                acc[0] += w * t.x; acc[1] += w * t.y;
            }
        }
    }

    float inv = 1.0f / den;
    if constexpr (CPL == 4) {
        float4 bv = ((const float4*)bias)[lane];
        float4 o;
        o.x = acc[0] * inv + bv.x;
        o.y = acc[1] * inv + bv.y;
        o.z = acc[2] * inv + bv.z;
        o.w = acc[3] * inv + bv.w;
        if (RELU) {
            o.x = fmaxf(o.x, 0.f); o.y = fmaxf(o.y, 0.f);
            o.z = fmaxf(o.z, 0.f); o.w = fmaxf(o.w, 0.f);
        }
        ((float4*)(out + (size_t)v * F))[lane] = o;
    } else {
        float2 bv = ((const float2*)bias)[lane];
        float2 o;
        o.x = acc[0] * inv + bv.x;
        o.y = acc[1] * inv + bv.y;
        if (RELU) { o.x = fmaxf(o.x, 0.f); o.y = fmaxf(o.y, 0.f); }
        ((float2*)(out + (size_t)v * F))[lane] = o;
    }
}

// ---------------- launch ------------------------------------------------------
extern "C" void kernel_launch(void* const* d_in, const int* in_sizes, int n_in,
                              void* d_out, int out_size) {
    const float* x      = (const float*)d_in[0];
    const void*  ei_raw = d_in[1];          // int32 or int64, probed at runtime
    const float* ew     = (const float*)d_in[2];
    const float *W0 = (const float*)d_in[3],  *as0 = (const float*)d_in[4],
                *ad0 = (const float*)d_in[5], *ae0 = (const float*)d_in[6],
                *We0 = (const float*)d_in[7], *b0  = (const float*)d_in[8];
    const float *W1 = (const float*)d_in[9],  *as1 = (const float*)d_in[10],
                *ad1 = (const float*)d_in[11], *ae1 = (const float*)d_in[12],
                *We1 = (const float*)d_in[13], *b1  = (const float*)d_in[14];
    const float *Wm = (const float*)d_in[15], *asm_ = (const float*)d_in[16],
                *adm = (const float*)d_in[17], *aem = (const float*)d_in[18],
                *Wem = (const float*)d_in[19], *bm  = (const float*)d_in[20];
    const float *Wl = (const float*)d_in[21], *asl = (const float*)d_in[22],
                *adl = (const float*)d_in[23], *bl  = (const float*)d_in[24];
    float* out = (float*)d_out;

    int *p_flag, *p_src, *p_dst, *p_cnt, *p_fill, *p_ptr, *p_bsum, *p_csrc;
    float *p_csw, *p_sumw, *p_loop, *p_xl, *p_h, *p_asrc, *p_adst, *p_c;
    cudaGetSymbolAddress((void**)&p_flag, g_flag64);
    cudaGetSymbolAddress((void**)&p_src,  g_src);
    cudaGetSymbolAddress((void**)&p_dst,  g_dst);
    cudaGetSymbolAddress((void**)&p_cnt,  g_cnt);
    cudaGetSymbolAddress((void**)&p_fill, g_fill);
    cudaGetSymbolAddress((void**)&p_ptr,  g_ptr);
    cudaGetSymbolAddress((void**)&p_bsum, g_bsum);
    cudaGetSymbolAddress((void**)&p_csrc, g_csrc);
    cudaGetSymbolAddress((void**)&p_csw,  g_csw);
    cudaGetSymbolAddress((void**)&p_sumw, g_sumw);
    cudaGetSymbolAddress((void**)&p_loop, g_loop);
    cudaGetSymbolAddress((void**)&p_xl,   g_xl);
    cudaGetSymbolAddress((void**)&p_h,    g_h);
    cudaGetSymbolAddress((void**)&p_asrc, g_asrc);
    cudaGetSymbolAddress((void**)&p_adst, g_adst);
    cudaGetSymbolAddress((void**)&p_c,    g_c);

    const int smem128 = (128 * 128 + 64 * 128) * 4;   // 96 KB
    const int smem64  = (128 * 64 + 64 * 128) * 4;    // 64 KB
    cudaFuncSetAttribute(k_gemm<128>, cudaFuncAttributeMaxDynamicSharedMemorySize, smem128);
    cudaFuncSetAttribute(k_gemm<64>,  cudaFuncAttributeMaxDynamicSharedMemorySize, smem64);

    cudaMemsetAsync(p_cnt,  0, NN * sizeof(int));
    cudaMemsetAsync(p_fill, 0, NN * sizeof(int));
    cudaMemsetAsync(p_sumw, 0, NN * sizeof(float));

    // dtype probe + canonicalize edge_index into int32 src/dst
    k_probe<<<1, 256>>>(ei_raw, p_flag);
    k_convert<<<(NE + 255) / 256, 256>>>(ei_raw, p_flag, p_src, p_dst, NE);

    // CSR build
    k_hist<<<(NE + 255) / 256, 256>>>(p_dst, p_cnt, NE);
    k_scan1<<<NB_SCAN, SCAN_B>>>(p_cnt, p_ptr, p_bsum, NN);
    k_scan2<<<1, 128>>>(p_bsum, NB_SCAN);
    k_scan3<<<NB_SCAN, SCAN_B>>>(p_ptr, p_bsum, NN);
    k_scatter<<<(NE + 255) / 256, 256>>>(p_src, p_dst, ew, p_ptr, p_fill,
                                         p_csrc, p_csw, p_sumw, NE);
    k_loopattr<<<(NN + 255) / 256, 256>>>(p_cnt, p_sumw, p_loop, NN);

    // per-layer edge-attention scalar c = dot(We, a_e)
    k_dot<<<1, 128>>>(We0, ae0, p_c + 0, 128);
    k_dot<<<1, 128>>>(We1, ae1, p_c + 1, 128);
    k_dot<<<1, 128>>>(Wem, aem, p_c + 2, 64);

    const int gemm_blocks = (NN + 63) / 64;
    const int agg_blocks  = (NN + 7) / 8;     // 8 warps/block, warp per node

    // layer 0: x -> h   (relu)
    k_gemm<128><<<gemm_blocks, 256, smem128>>>(x, W0, as0, ad0, p_xl, p_asrc, p_adst, NN);
    k_aggregate<128, true, true><<<agg_blocks, 256>>>(p_xl, p_asrc, p_adst, p_ptr, p_csrc,
                                                      p_csw, p_loop, p_c, 0, b0, p_h, NN);
    // layer 1: h -> h   (relu)
    k_gemm<128><<<gemm_blocks, 256, smem128>>>(p_h, W1, as1, ad1, p_xl, p_asrc, p_adst, NN);
    k_aggregate<128, true, true><<<agg_blocks, 256>>>(p_xl, p_asrc, p_adst, p_ptr, p_csrc,
                                                      p_csw, p_loop, p_c, 1, b1, p_h, NN);
    // mu: h -> out[0 : N*64]
    k_gemm<64><<<gemm_blocks, 256, smem64>>>(p_h, Wm, asm_, adm, p_xl, p_asrc, p_adst, NN);
    k_aggregate<64, true, false><<<agg_blocks, 256>>>(p_xl, p_asrc, p_adst, p_ptr, p_csrc,
                                                      p_csw, p_loop, p_c, 2, bm, out, NN);
    // logstd (no edge term): h -> out[N*64 : 2*N*64]
    k_gemm<64><<<gemm_blocks, 256, smem64>>>(p_h, Wl, asl, adl, p_xl, p_asrc, p_adst, NN);
    k_aggregate<64, false, false><<<agg_blocks, 256>>>(p_xl, p_asrc, p_adst, p_ptr, p_csrc,
                                                       p_csw, p_loop, p_c, 0, bl,
                                                       out + (size_t)NN * 64, NN);
}

// round 3
// speedup vs baseline: 1.1434x; 1.1434x over previous
#include <cuda_runtime.h>
#include <cuda_bf16.h>

// Problem constants (fixed by the dataset)
#define NN 100000
#define NE 1600000
#define SCAN_B 1024
#define NB_SCAN ((NN + SCAN_B - 1) / SCAN_B)   // 98

// ---------------- scratch (device globals; no allocation allowed) -------------
__device__ int   g_flag64;           // 1 if edge_index buffer is int64
__device__ int   g_src[NE];
__device__ int   g_dst[NE];
__device__ int   g_cnt[NN];
__device__ int   g_fill[NN];
__device__ int   g_ptr[NN + 1];
__device__ int   g_bsum[128];
__device__ int   g_csrc[NE];
__device__ float g_csw[NE];
__device__ float g_sumw[NN];
__device__ float g_loop[NN];
__device__ float g_xl[(size_t)NN * 128];
__device__ float g_h[(size_t)NN * 128];
__device__ float g_asrc[NN];
__device__ float g_adst[NN];
__device__ float g_c[4];

// ---------------- zero scratch -------------------------------------------------
__global__ void k_zero(int* __restrict__ cnt, int* __restrict__ fill,
                       float* __restrict__ sumw, int n) {
    int i = blockIdx.x * blockDim.x + threadIdx.x;
    if (i < n) { cnt[i] = 0; fill[i] = 0; sumw[i] = 0.f; }
}

// ---------------- dtype probe --------------------------------------------------
// Reads only the first 4096 entries interpreted as int64 (32 KB — within the
// buffer under either dtype). int32 data seen as int64 packs two random
// indices -> out of [0,NN) with overwhelming probability.
__global__ void k_probe(const void* __restrict__ ei_raw, int* __restrict__ flag) {
    __shared__ int bad;
    if (threadIdx.x == 0) bad = 0;
    __syncthreads();
    const long long* p = (const long long*)ei_raw;
    for (int i = threadIdx.x; i < 4096; i += blockDim.x) {
        long long v = p[i];
        if (v < 0 || v >= (long long)NN) bad = 1;
    }
    __syncthreads();
    if (threadIdx.x == 0) *flag = bad ? 0 : 1;
}

// convert + degree histogram fused
__global__ void k_convert(const void* __restrict__ ei_raw, const int* __restrict__ flag,
                          int* __restrict__ src, int* __restrict__ dst,
                          int* __restrict__ cnt, int E) {
    int e = blockIdx.x * blockDim.x + threadIdx.x;
    if (e >= E) return;
    int s, d;
    if (__ldg(flag)) {
        const long long* p = (const long long*)ei_raw;
        s = (int)p[e]; d = (int)p[E + e];
    } else {
        const int* p = (const int*)ei_raw;
        s = p[e]; d = p[E + e];
    }
    src[e] = s; dst[e] = d;
    atomicAdd(&cnt[d], 1);
}

// ---------------- CSR build ---------------------------------------------------
__global__ void k_scan1(const int* __restrict__ cnt, int* __restrict__ ptr,
                        int* __restrict__ bsum, int n) {
    __shared__ int sm[SCAN_B];
    int i = blockIdx.x * SCAN_B + threadIdx.x;
    int v = (i < n) ? cnt[i] : 0;
    sm[threadIdx.x] = v;
    __syncthreads();
    for (int off = 1; off < SCAN_B; off <<= 1) {
        int t = (threadIdx.x >= off) ? sm[threadIdx.x - off] : 0;
        __syncthreads();
        sm[threadIdx.x] += t;
        __syncthreads();
    }
    if (i < n) ptr[i + 1] = sm[threadIdx.x];
    if (threadIdx.x == SCAN_B - 1) bsum[blockIdx.x] = sm[SCAN_B - 1];
    if (i == 0) ptr[0] = 0;
}

// fused scan2+scan3: each block redundantly sums bsum[j<bid], adds to its slice
__global__ void k_scan23(int* __restrict__ ptr, const int* __restrict__ bsum, int n) {
    __shared__ int sm[128];
    int t = threadIdx.x;
    if (t < 128) sm[t] = (t < (int)blockIdx.x && t < NB_SCAN) ? bsum[t] : 0;
    __syncthreads();
    for (int off = 64; off; off >>= 1) {
        if (t < off) sm[t] += sm[t + off];
        __syncthreads();
    }
    int offs = sm[0];
    int i = blockIdx.x * SCAN_B + t;
    if (i < n) ptr[i + 1] += offs;
}

__global__ void k_scatter(const int* __restrict__ src, const int* __restrict__ dst,
                          const float* __restrict__ ew,
                          const int* __restrict__ ptr, int* __restrict__ fill,
                          int* __restrict__ csrc, float* __restrict__ csw,
                          float* __restrict__ sumw, int E) {
    int e = blockIdx.x * blockDim.x + threadIdx.x;
    if (e >= E) return;
    int s = src[e];
    int d = dst[e];
    float w = ew[e];
    int pos = ptr[d] + atomicAdd(&fill[d], 1);
    csrc[pos] = s;
    csw[pos] = w;
    atomicAdd(&sumw[d], w);
}

// fused: 3 edge-attention dots (block 0) + self-loop attr (blocks 1..)
__global__ void k_misc(const int* __restrict__ cnt, const float* __restrict__ sumw,
                       float* __restrict__ la,
                       const float* __restrict__ We0, const float* __restrict__ ae0,
                       const float* __restrict__ We1, const float* __restrict__ ae1,
                       const float* __restrict__ Wem, const float* __restrict__ aem,
                       float* __restrict__ c, int n) {
    if (blockIdx.x == 0) {
        int w = threadIdx.x >> 5, lane = threadIdx.x & 31;
        if (w < 3) {
            const float* A = (w == 0) ? We0 : ((w == 1) ? We1 : Wem);
            const float* B = (w == 0) ? ae0 : ((w == 1) ? ae1 : aem);
            int len = (w == 2) ? 64 : 128;
            float p = 0.f;
            for (int i = lane; i < len; i += 32) p += A[i] * B[i];
#pragma unroll
            for (int off = 16; off; off >>= 1) p += __shfl_xor_sync(0xffffffffu, p, off);
            if (lane == 0) c[w] = p;
        }
    } else {
        int i = (blockIdx.x - 1) * blockDim.x + threadIdx.x;
        if (i < n) {
            int cc = cnt[i];
            la[i] = (cc > 0) ? (sumw[i] / (float)cc) : 0.0f;
        }
    }
}

// ---------------- GEMM: Y[n,NOUT] = X[n,128] @ W[128,NOUT] --------------------
// fp32x2 packed FMA (fma.rn.f32x2): 2x fp32 throughput, bit-identical rounding.
// Fused per-row attention dots a_src = y.a_s, a_dst = y.a_d.
template <int NOUT>
__global__ void k_gemm(const float* __restrict__ X, const float* __restrict__ W,
                       const float* __restrict__ a_s, const float* __restrict__ a_d,
                       float* __restrict__ Y, float* __restrict__ asrc,
                       float* __restrict__ adst, int n) {
    constexpr int CPL = NOUT / 32;   // cols per lane (4 or 2)
    constexpr int NP  = CPL / 2;     // packed accumulators per row (2 or 1)
    extern __shared__ float smem[];
    float* ws = smem;                 // [128 * NOUT]
    float* xs = smem + 128 * NOUT;    // [64 * 128]

    int tid = threadIdx.x;
    int base = blockIdx.x * 64;

    for (int i = tid; i < 128 * NOUT / 4; i += 256)
        ((float4*)ws)[i] = ((const float4*)W)[i];
    for (int i = tid; i < 64 * 32; i += 256) {
        int r = i >> 5, c4 = i & 31;
        int row = base + r;
        float4 t = make_float4(0.f, 0.f, 0.f, 0.f);
        if (row < n) t = ((const float4*)(X + (size_t)row * 128))[c4];
        ((float4*)(xs + r * 128))[c4] = t;
    }
    __syncthreads();

    int warp = tid >> 5, lane = tid & 31;
    unsigned long long acc[8][NP];
#pragma unroll
    for (int r = 0; r < 8; r++)
#pragma unroll
        for (int p = 0; p < NP; p++) acc[r][p] = 0ull;

    const float* xrow = xs + warp * 8 * 128;

    for (int k = 0; k < 128; k += 2) {
        unsigned long long w0a, w0b = 0, w1a, w1b = 0;
        if constexpr (NP == 2) {
            ulonglong2 wv0 = *(const ulonglong2*)(ws + k * NOUT + lane * 4);
            ulonglong2 wv1 = *(const ulonglong2*)(ws + (k + 1) * NOUT + lane * 4);
            w0a = wv0.x; w0b = wv0.y; w1a = wv1.x; w1b = wv1.y;
        } else {
            w0a = *(const unsigned long long*)(ws + k * NOUT + lane * 2);
            w1a = *(const unsigned long long*)(ws + (k + 1) * NOUT + lane * 2);
        }
#pragma unroll
        for (int r = 0; r < 8; r++) {
            float2 xv = *(const float2*)(xrow + r * 128 + k);
            unsigned long long x0, x1;
            asm("mov.b64 %0, {%1, %1};" : "=l"(x0) : "r"(__float_as_uint(xv.x)));
            asm("mov.b64 %0, {%1, %1};" : "=l"(x1) : "r"(__float_as_uint(xv.y)));
            asm("fma.rn.f32x2 %0, %1, %2, %0;" : "+l"(acc[r][0]) : "l"(x0), "l"(w0a));
            if constexpr (NP == 2)
                asm("fma.rn.f32x2 %0, %1, %2, %0;" : "+l"(acc[r][1]) : "l"(x0), "l"(w0b));
            asm("fma.rn.f32x2 %0, %1, %2, %0;" : "+l"(acc[r][0]) : "l"(x1), "l"(w1a));
            if constexpr (NP == 2)
                asm("fma.rn.f32x2 %0, %1, %2, %0;" : "+l"(acc[r][1]) : "l"(x1), "l"(w1b));
        }
    }

    // attention vectors per-lane chunks
    float av[CPL], dv[CPL];
#pragma unroll
    for (int j = 0; j < CPL; j++) {
        av[j] = a_s[lane * CPL + j];
        dv[j] = a_d[lane * CPL + j];
    }

#pragma unroll
    for (int r = 0; r < 8; r++) {
        int row = base + warp * 8 + r;
        float o[CPL];
#pragma unroll
        for (int p = 0; p < NP; p++) {
            unsigned int lo, hi;
            asm("mov.b64 {%0, %1}, %2;" : "=r"(lo), "=r"(hi) : "l"(acc[r][p]));
            o[p * 2]     = __uint_as_float(lo);
            o[p * 2 + 1] = __uint_as_float(hi);
        }
        float pa = 0.f, pd = 0.f;
#pragma unroll
        for (int j = 0; j < CPL; j++) { pa += o[j] * av[j]; pd += o[j] * dv[j]; }
#pragma unroll
        for (int off = 16; off; off >>= 1) {
            pa += __shfl_xor_sync(0xffffffffu, pa, off);
            pd += __shfl_xor_sync(0xffffffffu, pd, off);
        }
        if (row < n) {
            if constexpr (CPL == 4) {
                float4 ov = make_float4(o[0], o[1], o[2], o[3]);
                ((float4*)(Y + (size_t)row * NOUT))[lane] = ov;
            } else {
                float2 ov = make_float2(o[0], o[1]);
                ((float2*)(Y + (size_t)row * NOUT))[lane] = ov;
            }
            if (lane == 0) { asrc[row] = pa; adst[row] = pd; }
        }
    }
}

// ---------------- aggregation: per-dst softmax + weighted gather --------------
__device__ __forceinline__ float lrelu(float a) { return a > 0.f ? a : 0.2f * a; }

template <int F, bool EDGE, bool RELU>
__global__ void k_aggregate(const float* __restrict__ xl, const float* __restrict__ asrc,
                            const float* __restrict__ adst, const int* __restrict__ ptr,
                            const int* __restrict__ csrc, const float* __restrict__ csw,
                            const float* __restrict__ la, const float* __restrict__ cvec,
                            int cidx, const float* __restrict__ bias,
                            float* __restrict__ out, int n) {
    constexpr int CPL = F / 32;   // 4 for F=128, 2 for F=64
    int wid = (blockIdx.x * blockDim.x + threadIdx.x) >> 5;
    int lane = threadIdx.x & 31;
    if (wid >= n) return;
    int v = wid;

    float c = EDGE ? cvec[cidx] : 0.f;
    float adv = adst[v];

    // self loop
    float a0 = asrc[v] + adv;
    if (EDGE) a0 += la[v] * c;
    a0 = lrelu(a0);
    float m = a0, den = 1.0f;

    float acc[CPL];
    {
        const float* row = xl + (size_t)v * F;
        if constexpr (CPL == 4) {
            float4 t = ((const float4*)row)[lane];
            acc[0] = t.x; acc[1] = t.y; acc[2] = t.z; acc[3] = t.w;
        } else {
            float2 t = ((const float2*)row)[lane];
            acc[0] = t.x; acc[1] = t.y;
        }
    }

    int rs = ptr[v], re = ptr[v + 1];
    for (int b = rs; b < re; b += 32) {
        int e = b + lane;
        float al = 0.f;
        int sIdx = 0;
        if (e < re) {
            sIdx = csrc[e];
            float a = asrc[sIdx] + adv;
            if (EDGE) a += csw[e] * c;
            al = lrelu(a);
        }
        int cnt = min(32, re - b);
        for (int j = 0; j < cnt; j++) {
            float a = __shfl_sync(0xffffffffu, al, j);
            int s = __shfl_sync(0xffffffffu, sIdx, j);
            float w;
            if (a > m) {           // warp-uniform branch
                float r = __expf(m - a);
                den *= r;
#pragma unroll
                for (int i = 0; i < CPL; i++) acc[i] *= r;
                m = a;
                w = 1.0f;
            } else {
                w = __expf(a - m);
            }
            den += w;
            const float* srow = xl + (size_t)s * F;
            if constexpr (CPL == 4) {
                float4 t = ((const float4*)srow)[lane];
                acc[0] += w * t.x; acc[1] += w * t.y;
                acc[2] += w * t.z; acc[3] += w * t.w;
            } else {
                float2 t = ((const float2*)srow)[lane];
                acc[0] += w * t.x; acc[1] += w * t.y;
            }
        }
    }

    float inv = 1.0f / den;
    if constexpr (CPL == 4) {
        float4 bv = ((const float4*)bias)[lane];
        float4 o;
        o.x = acc[0] * inv + bv.x;
        o.y = acc[1] * inv + bv.y;
        o.z = acc[2] * inv + bv.z;
        o.w = acc[3] * inv + bv.w;
        if (RELU) {
            o.x = fmaxf(o.x, 0.f); o.y = fmaxf(o.y, 0.f);
            o.z = fmaxf(o.z, 0.f); o.w = fmaxf(o.w, 0.f);
        }
        ((float4*)(out + (size_t)v * F))[lane] = o;
    } else {
        float2 bv = ((const float2*)bias)[lane];
        float2 o;
        o.x = acc[0] * inv + bv.x;
        o.y = acc[1] * inv + bv.y;
        if (RELU) { o.x = fmaxf(o.x, 0.f); o.y = fmaxf(o.y, 0.f); }
        ((float2*)(out + (size_t)v * F))[lane] = o;
    }
}

// ---------------- launch ------------------------------------------------------
extern "C" void kernel_launch(void* const* d_in, const int* in_sizes, int n_in,
                              void* d_out, int out_size) {
    const float* x      = (const float*)d_in[0];
    const void*  ei_raw = d_in[1];          // int32 or int64, probed at runtime
    const float* ew     = (const float*)d_in[2];
    const float *W0 = (const float*)d_in[3],  *as0 = (const float*)d_in[4],
                *ad0 = (const float*)d_in[5], *ae0 = (const float*)d_in[6],
                *We0 = (const float*)d_in[7], *b0  = (const float*)d_in[8];
    const float *W1 = (const float*)d_in[9],  *as1 = (const float*)d_in[10],
                *ad1 = (const float*)d_in[11], *ae1 = (const float*)d_in[12],
                *We1 = (const float*)d_in[13], *b1  = (const float*)d_in[14];
    const float *Wm = (const float*)d_in[15], *asm_ = (const float*)d_in[16],
                *adm = (const float*)d_in[17], *aem = (const float*)d_in[18],
                *Wem = (const float*)d_in[19], *bm  = (const float*)d_in[20];
    const float *Wl = (const float*)d_in[21], *asl = (const float*)d_in[22],
                *adl = (const float*)d_in[23], *bl  = (const float*)d_in[24];
    float* out = (float*)d_out;

    int *p_flag, *p_src, *p_dst, *p_cnt, *p_fill, *p_ptr, *p_bsum, *p_csrc;
    float *p_csw, *p_sumw, *p_loop, *p_xl, *p_h, *p_asrc, *p_adst, *p_c;
    cudaGetSymbolAddress((void**)&p_flag, g_flag64);
    cudaGetSymbolAddress((void**)&p_src,  g_src);
    cudaGetSymbolAddress((void**)&p_dst,  g_dst);
    cudaGetSymbolAddress((void**)&p_cnt,  g_cnt);
    cudaGetSymbolAddress((void**)&p_fill, g_fill);
    cudaGetSymbolAddress((void**)&p_ptr,  g_ptr);
    cudaGetSymbolAddress((void**)&p_bsum, g_bsum);
    cudaGetSymbolAddress((void**)&p_csrc, g_csrc);
    cudaGetSymbolAddress((void**)&p_csw,  g_csw);
    cudaGetSymbolAddress((void**)&p_sumw, g_sumw);
    cudaGetSymbolAddress((void**)&p_loop, g_loop);
    cudaGetSymbolAddress((void**)&p_xl,   g_xl);
    cudaGetSymbolAddress((void**)&p_h,    g_h);
    cudaGetSymbolAddress((void**)&p_asrc, g_asrc);
    cudaGetSymbolAddress((void**)&p_adst, g_adst);
    cudaGetSymbolAddress((void**)&p_c,    g_c);

    const int smem128 = (128 * 128 + 64 * 128) * 4;   // 96 KB
    const int smem64  = (128 * 64 + 64 * 128) * 4;    // 64 KB
    cudaFuncSetAttribute(k_gemm<128>, cudaFuncAttributeMaxDynamicSharedMemorySize, smem128);
    cudaFuncSetAttribute(k_gemm<64>,  cudaFuncAttributeMaxDynamicSharedMemorySize, smem64);

    const int gemm_blocks = (NN + 63) / 64;
    const int agg_blocks  = (NN + 7) / 8;     // 8 warps/block, warp per node

    // 1: zero scratch
    k_zero<<<(NN + 255) / 256, 256>>>(p_cnt, p_fill, p_sumw, NN);
    // 2: dtype probe
    k_probe<<<1, 256>>>(ei_raw, p_flag);
    // 3: convert + degree histogram
    k_convert<<<(NE + 255) / 256, 256>>>(ei_raw, p_flag, p_src, p_dst, p_cnt, NE);
    // 4-5: prefix scan of degrees -> ptr
    k_scan1<<<NB_SCAN, SCAN_B>>>(p_cnt, p_ptr, p_bsum, NN);
    k_scan23<<<NB_SCAN, SCAN_B>>>(p_ptr, p_bsum, NN);
    // 6: layer-0 GEMM (independent of CSR; placed here so ncu -s 5 -c 1 captures it)
    k_gemm<128><<<gemm_blocks, 256, smem128>>>(x, W0, as0, ad0, p_xl, p_asrc, p_adst, NN);
    // 7: scatter into CSR
    k_scatter<<<(NE + 255) / 256, 256>>>(p_src, p_dst, ew, p_ptr, p_fill,
                                         p_csrc, p_csw, p_sumw, NE);
    // 8: edge-attention scalars + self-loop attrs
    k_misc<<<1 + (NN + 255) / 256, 256>>>(p_cnt, p_sumw, p_loop,
                                          We0, ae0, We1, ae1, Wem, aem, p_c, NN);

    // layer 0 aggregate (relu)
    k_aggregate<128, true, true><<<agg_blocks, 256>>>(p_xl, p_asrc, p_adst, p_ptr, p_csrc,
                                                      p_csw, p_loop, p_c, 0, b0, p_h, NN);
    // layer 1: h -> h (relu)
    k_gemm<128><<<gemm_blocks, 256, smem128>>>(p_h, W1, as1, ad1, p_xl, p_asrc, p_adst, NN);
    k_aggregate<128, true, true><<<agg_blocks, 256>>>(p_xl, p_asrc, p_adst, p_ptr, p_csrc,
                                                      p_csw, p_loop, p_c, 1, b1, p_h, NN);
    // mu: h -> out[0 : N*64]
    k_gemm<64><<<gemm_blocks, 256, smem64>>>(p_h, Wm, asm_, adm, p_xl, p_asrc, p_adst, NN);
    k_aggregate<64, true, false><<<agg_blocks, 256>>>(p_xl, p_asrc, p_adst, p_ptr, p_csrc,
                                                      p_csw, p_loop, p_c, 2, bm, out, NN);
    // logstd (no edge term): h -> out[N*64 : 2*N*64]
    k_gemm<64><<<gemm_blocks, 256, smem64>>>(p_h, Wl, asl, adl, p_xl, p_asrc, p_adst, NN);
    k_aggregate<64, false, false><<<agg_blocks, 256>>>(p_xl, p_asrc, p_adst, p_ptr, p_csrc,
                                                       p_csw, p_loop, p_c, 0, bl,
                                                       out + (size_t)NN * 64, NN);
}

// round 5
// speedup vs baseline: 1.4752x; 1.2902x over previous
#include <cuda_runtime.h>
#include <cuda_bf16.h>
#include <cstdint>

// Problem constants (fixed by the dataset)
#define NN 100000
#define NE 1600000
#define SCAN_B 1024
#define NB_SCAN ((NN + SCAN_B - 1) / SCAN_B)   // 98
#define NTILES ((NN + 127) / 128)              // 782
#define MMA_GRID 148

// ---------------- scratch (device globals; no allocation allowed) -------------
__device__ int   g_flag64;           // 1 if edge_index buffer is int64
__device__ int   g_src[NE];
__device__ int   g_dst[NE];
__device__ int   g_cnt[NN];
__device__ int   g_fill[NN];
__device__ int   g_ptr[NN + 1];
__device__ int   g_bsum[128];
__device__ int   g_csrc[NE];
__device__ float g_csw[NE];
__device__ float g_sumw[NN];
__device__ float g_loop[NN];
__device__ float g_xl[(size_t)NN * 128];
__device__ float g_h[(size_t)NN * 128];
__device__ float g_asrc[NN];
__device__ float g_adst[NN];
__device__ float g_c[4];
__device__ __nv_bfloat16 g_bh[(size_t)NN * 128];
__device__ __nv_bfloat16 g_bl[(size_t)NN * 128];
__device__ __nv_bfloat16 g_wh[49152];
__device__ __nv_bfloat16 g_wl[49152];

// ---------------- helpers -------------------------------------------------------
__device__ __forceinline__ uint32_t s2u(const void* p) {
    uint32_t a;
    asm("{ .reg .u64 t; cvta.to.shared.u64 t, %1; cvt.u32.u64 %0, t; }"
        : "=r"(a) : "l"(p));
    return a;
}
__device__ __forceinline__ void cp16(uint32_t saddr, const void* g, int sz) {
    asm volatile("cp.async.cg.shared.global [%0], [%1], 16, %2;"
                 :: "r"(saddr), "l"(g), "r"(sz));
}
__device__ __forceinline__ void cp_commit() {
    asm volatile("cp.async.commit_group;" ::: "memory");
}
__device__ __forceinline__ void cp_wait1() {
    asm volatile("cp.async.wait_group 1;" ::: "memory");
}
__device__ __forceinline__ void cp_wait0() {
    asm volatile("cp.async.wait_group 0;" ::: "memory");
}
__device__ __forceinline__ void ldsm4(uint32_t* r, uint32_t addr) {
    asm volatile("ldmatrix.sync.aligned.m8n8.x4.shared.b16 {%0,%1,%2,%3}, [%4];"
                 : "=r"(r[0]), "=r"(r[1]), "=r"(r[2]), "=r"(r[3]) : "r"(addr));
}
__device__ __forceinline__ void mma16816(float* d, const uint32_t* a, const uint32_t* b) {
    asm volatile(
        "mma.sync.aligned.m16n8k16.row.col.f32.bf16.bf16.f32 "
        "{%0,%1,%2,%3}, {%4,%5,%6,%7}, {%8,%9}, {%0,%1,%2,%3};"
        : "+f"(d[0]), "+f"(d[1]), "+f"(d[2]), "+f"(d[3])
        : "r"(a[0]), "r"(a[1]), "r"(a[2]), "r"(a[3]), "r"(b[0]), "r"(b[1]));
}

// async-load a [ROWS x 128] bf16 K-major tile into smem with padded row stride
// 136 bf16 (272 bytes): conflict-free for ldmatrix (rows shift by 4 banks).
template <int ROWS, int NTHR>
__device__ __forceinline__ void load_tile(uint32_t sbase, const __nv_bfloat16* src,
                                          size_t row0, int nrows, int tid) {
#pragma unroll 4
    for (int c = tid; c < ROWS * 16; c += NTHR) {
        int row = c >> 4, kc = c & 15;
        uint32_t off = (uint32_t)row * 272 + kc * 16;
        size_t grow = (row < nrows) ? (row0 + row) : row0;
        cp16(sbase + off, src + grow * 128 + kc * 8, (row < nrows) ? 16 : 0);
    }
}

// ---------------- GEMM via mma.sync bf16x3 split --------------------------------
// Y[n, NOUT] = X[n,128] @ W[128,NOUT]; X = Ah+Al (bf16 hi/lo), Wt = Bh+Bl
// stored [NOUT][128] K-major. 3 passes AhBh + AhBl + AlBh, fp32 accumulate.
// Fused epilogue: per-row attention dots asrc = y.a_s, adst = y.a_d.
template <int NOUT>
__global__ void __launch_bounds__(256, 1)
k_mma(const __nv_bfloat16* __restrict__ Ah, const __nv_bfloat16* __restrict__ Al,
      const __nv_bfloat16* __restrict__ Bh, const __nv_bfloat16* __restrict__ Bl,
      const float* __restrict__ a_s, const float* __restrict__ a_d,
      float* __restrict__ Y, float* __restrict__ asrc, float* __restrict__ adst,
      int n, int ntiles) {
    constexpr int NT = NOUT / 8;               // n-tiles (16 or 8)
    constexpr int WB = NOUT * 272;             // bytes per W split half
    constexpr int AB = 128 * 272;              // bytes per A split half (34816)
    extern __shared__ __align__(16) char smem[];
    char* sWh = smem;
    char* sWl = smem + WB;
    char* sA  = smem + 2 * WB;                 // 2 bufs x (Ah | Al)
    float* sAtt = (float*)(smem + 2 * WB + 4 * AB);

    int tid = threadIdx.x, warp = tid >> 5, lane = tid & 31;

    for (int i = tid; i < NOUT; i += 256) { sAtt[i] = a_s[i]; sAtt[NOUT + i] = a_d[i]; }

    uint32_t uWh = s2u(sWh), uWl = s2u(sWl), uA = s2u(sA);

    // prologue: W (hi+lo), then A tile 0
    load_tile<NOUT, 256>(uWh, Bh, 0, NOUT, tid);
    load_tile<NOUT, 256>(uWl, Bl, 0, NOUT, tid);
    cp_commit();
    {
        int t0 = blockIdx.x;
        int nr = min(128, n - t0 * 128);
        load_tile<128, 256>(uA, Ah, (size_t)t0 * 128, nr, tid);
        load_tile<128, 256>(uA + AB, Al, (size_t)t0 * 128, nr, tid);
        cp_commit();
    }

    // ldmatrix address offsets (within a split half)
    int mi = lane >> 3, l7 = lane & 7;
    uint32_t aoff = (uint32_t)(warp * 16 + ((mi & 1) << 3) + l7) * 272 + ((mi >> 1) << 3) * 2;
    uint32_t boff = (uint32_t)(((mi >> 1) << 3) + l7) * 272 + ((mi & 1) << 3) * 2;

    int buf = 0;
    for (int t = blockIdx.x; t < ntiles; t += gridDim.x) {
        int tn = t + gridDim.x;
        if (tn < ntiles) {
            int nr = min(128, n - tn * 128);
            uint32_t nb = uA + (buf ^ 1) * 2 * AB;
            load_tile<128, 256>(nb, Ah, (size_t)tn * 128, nr, tid);
            load_tile<128, 256>(nb + AB, Al, (size_t)tn * 128, nr, tid);
            cp_commit();
            cp_wait1();
        } else {
            cp_wait0();
        }
        __syncthreads();

        uint32_t uAh = uA + buf * 2 * AB;
        uint32_t uAl = uAh + AB;

        float acc[NT][4];
#pragma unroll
        for (int j = 0; j < NT; j++)
#pragma unroll
            for (int q = 0; q < 4; q++) acc[j][q] = 0.f;

#pragma unroll
        for (int ks = 0; ks < 8; ks++) {
            uint32_t kb = ks * 32;   // 16 bf16 = 32 bytes per k-step
            uint32_t ah[4], al_[4];
            ldsm4(ah, uAh + aoff + kb);
            ldsm4(al_, uAl + aoff + kb);
#pragma unroll
            for (int j = 0; j < NT; j += 2) {
                uint32_t bh[4], bl_[4];
                uint32_t bo = boff + (uint32_t)j * 8 * 272 + kb;
                ldsm4(bh, uWh + bo);
                ldsm4(bl_, uWl + bo);
                mma16816(acc[j],     ah,  bh);
                mma16816(acc[j + 1], ah,  bh + 2);
                mma16816(acc[j],     ah,  bl_);
                mma16816(acc[j + 1], ah,  bl_ + 2);
                mma16816(acc[j],     al_, bh);
                mma16816(acc[j + 1], al_, bh + 2);
            }
        }

        // epilogue: C frag (r0=row l/4, r1=row+8; cols j*8 + 2*(l%4))
        int r0 = warp * 16 + (lane >> 2);
        int node0 = t * 128 + r0;
        int node1 = node0 + 8;
        bool v0 = node0 < n, v1 = node1 < n;
        float pa0 = 0.f, pd0 = 0.f, pa1 = 0.f, pd1 = 0.f;
        int cb = (lane & 3) * 2;
#pragma unroll
        for (int j = 0; j < NT; j++) {
            int c = j * 8 + cb;
            float s0 = sAtt[c], s1 = sAtt[c + 1];
            float d0 = sAtt[NOUT + c], d1 = sAtt[NOUT + c + 1];
            pa0 += acc[j][0] * s0 + acc[j][1] * s1;
            pd0 += acc[j][0] * d0 + acc[j][1] * d1;
            pa1 += acc[j][2] * s0 + acc[j][3] * s1;
            pd1 += acc[j][2] * d0 + acc[j][3] * d1;
            if (v0) *(float2*)(Y + (size_t)node0 * NOUT + c) = make_float2(acc[j][0], acc[j][1]);
            if (v1) *(float2*)(Y + (size_t)node1 * NOUT + c) = make_float2(acc[j][2], acc[j][3]);
        }
#pragma unroll
        for (int o = 1; o <= 2; o <<= 1) {
            pa0 += __shfl_xor_sync(0xffffffffu, pa0, o);
            pd0 += __shfl_xor_sync(0xffffffffu, pd0, o);
            pa1 += __shfl_xor_sync(0xffffffffu, pa1, o);
            pd1 += __shfl_xor_sync(0xffffffffu, pd1, o);
        }
        if ((lane & 3) == 0) {
            if (v0) { asrc[node0] = pa0; adst[node0] = pd0; }
            if (v1) { asrc[node1] = pa1; adst[node1] = pd1; }
        }
        __syncthreads();
        buf ^= 1;
    }
}

// ---------------- fp32 -> bf16 hi/lo split -------------------------------------
__global__ void k_convx(const float* __restrict__ s, __nv_bfloat16* __restrict__ bh,
                        __nv_bfloat16* __restrict__ bl, int n4) {
    int i = blockIdx.x * blockDim.x + threadIdx.x;
    if (i >= n4) return;
    float4 v = ((const float4*)s)[i];
    __nv_bfloat16 h0 = __float2bfloat16(v.x), h1 = __float2bfloat16(v.y);
    __nv_bfloat16 h2 = __float2bfloat16(v.z), h3 = __float2bfloat16(v.w);
    __nv_bfloat16 l0 = __float2bfloat16(v.x - __bfloat162float(h0));
    __nv_bfloat16 l1 = __float2bfloat16(v.y - __bfloat162float(h1));
    __nv_bfloat16 l2 = __float2bfloat16(v.z - __bfloat162float(h2));
    __nv_bfloat16 l3 = __float2bfloat16(v.w - __bfloat162float(h3));
    ((__nv_bfloat162*)bh)[i * 2]     = __nv_bfloat162(h0, h1);
    ((__nv_bfloat162*)bh)[i * 2 + 1] = __nv_bfloat162(h2, h3);
    ((__nv_bfloat162*)bl)[i * 2]     = __nv_bfloat162(l0, l1);
    ((__nv_bfloat162*)bl)[i * 2 + 1] = __nv_bfloat162(l2, l3);
}

// transpose + split all 4 weight matrices into wt[n*128+k] hi/lo
// offsets: W0t=0, W1t=16384, Wmt=32768, Wlt=40960 (total 49152)
__global__ void k_convw(const float* __restrict__ W0, const float* __restrict__ W1,
                        const float* __restrict__ Wm, const float* __restrict__ Wl,
                        __nv_bfloat16* __restrict__ wh, __nv_bfloat16* __restrict__ wl_) {
    int i = blockIdx.x * blockDim.x + threadIdx.x;
    if (i >= 49152) return;
    float v;
    if (i < 16384)      { int j = i;         int nn = j >> 7, k = j & 127; v = W0[k * 128 + nn]; }
    else if (i < 32768) { int j = i - 16384; int nn = j >> 7, k = j & 127; v = W1[k * 128 + nn]; }
    else if (i < 40960) { int j = i - 32768; int nn = j >> 7, k = j & 127; v = Wm[k * 64 + nn]; }
    else                { int j = i - 40960; int nn = j >> 7, k = j & 127; v = Wl[k * 64 + nn]; }
    __nv_bfloat16 h = __float2bfloat16(v);
    wh[i] = h;
    wl_[i] = __float2bfloat16(v - __bfloat162float(h));
}

// ---------------- zero scratch -------------------------------------------------
__global__ void k_zero(int* __restrict__ cnt, int* __restrict__ fill,
                       float* __restrict__ sumw, int n) {
    int i = blockIdx.x * blockDim.x + threadIdx.x;
    if (i < n) { cnt[i] = 0; fill[i] = 0; sumw[i] = 0.f; }
}

// ---------------- dtype probe --------------------------------------------------
__global__ void k_probe(const void* __restrict__ ei_raw, int* __restrict__ flag) {
    __shared__ int bad;
    if (threadIdx.x == 0) bad = 0;
    __syncthreads();
    const long long* p = (const long long*)ei_raw;
    for (int i = threadIdx.x; i < 4096; i += blockDim.x) {
        long long v = p[i];
        if (v < 0 || v >= (long long)NN) bad = 1;
    }
    __syncthreads();
    if (threadIdx.x == 0) *flag = bad ? 0 : 1;
}

__global__ void k_convert(const void* __restrict__ ei_raw, const int* __restrict__ flag,
                          int* __restrict__ src, int* __restrict__ dst,
                          int* __restrict__ cnt, int E) {
    int e = blockIdx.x * blockDim.x + threadIdx.x;
    if (e >= E) return;
    int s, d;
    if (__ldg(flag)) {
        const long long* p = (const long long*)ei_raw;
        s = (int)p[e]; d = (int)p[E + e];
    } else {
        const int* p = (const int*)ei_raw;
        s = p[e]; d = p[E + e];
    }
    src[e] = s; dst[e] = d;
    atomicAdd(&cnt[d], 1);
}

// ---------------- CSR build ---------------------------------------------------
__global__ void k_scan1(const int* __restrict__ cnt, int* __restrict__ ptr,
                        int* __restrict__ bsum, int n) {
    __shared__ int sm[SCAN_B];
    int i = blockIdx.x * SCAN_B + threadIdx.x;
    int v = (i < n) ? cnt[i] : 0;
    sm[threadIdx.x] = v;
    __syncthreads();
    for (int off = 1; off < SCAN_B; off <<= 1) {
        int t = (threadIdx.x >= off) ? sm[threadIdx.x - off] : 0;
        __syncthreads();
        sm[threadIdx.x] += t;
        __syncthreads();
    }
    if (i < n) ptr[i + 1] = sm[threadIdx.x];
    if (threadIdx.x == SCAN_B - 1) bsum[blockIdx.x] = sm[SCAN_B - 1];
    if (i == 0) ptr[0] = 0;
}

__global__ void k_scan23(int* __restrict__ ptr, const int* __restrict__ bsum, int n) {
    __shared__ int sm[128];
    int t = threadIdx.x;
    if (t < 128) sm[t] = (t < (int)blockIdx.x && t < NB_SCAN) ? bsum[t] : 0;
    __syncthreads();
    for (int off = 64; off; off >>= 1) {
        if (t < off) sm[t] += sm[t + off];
        __syncthreads();
    }
    int offs = sm[0];
    int i = blockIdx.x * SCAN_B + t;
    if (i < n) ptr[i + 1] += offs;
}

__global__ void k_scatter(const int* __restrict__ src, const int* __restrict__ dst,
                          const float* __restrict__ ew,
                          const int* __restrict__ ptr, int* __restrict__ fill,
                          int* __restrict__ csrc, float* __restrict__ csw,
                          float* __restrict__ sumw, int E) {
    int e = blockIdx.x * blockDim.x + threadIdx.x;
    if (e >= E) return;
    int s = src[e];
    int d = dst[e];
    float w = ew[e];
    int pos = ptr[d] + atomicAdd(&fill[d], 1);
    csrc[pos] = s;
    csw[pos] = w;
    atomicAdd(&sumw[d], w);
}

// fused: 3 edge-attention dots (block 0) + self-loop attr (blocks 1..)
__global__ void k_misc(const int* __restrict__ cnt, const float* __restrict__ sumw,
                       float* __restrict__ la,
                       const float* __restrict__ We0, const float* __restrict__ ae0,
                       const float* __restrict__ We1, const float* __restrict__ ae1,
                       const float* __restrict__ Wem, const float* __restrict__ aem,
                       float* __restrict__ c, int n) {
    if (blockIdx.x == 0) {
        int w = threadIdx.x >> 5, lane = threadIdx.x & 31;
        if (w < 3) {
            const float* A = (w == 0) ? We0 : ((w == 1) ? We1 : Wem);
            const float* B = (w == 0) ? ae0 : ((w == 1) ? ae1 : aem);
            int len = (w == 2) ? 64 : 128;
            float p = 0.f;
            for (int i = lane; i < len; i += 32) p += A[i] * B[i];
#pragma unroll
            for (int off = 16; off; off >>= 1) p += __shfl_xor_sync(0xffffffffu, p, off);
            if (lane == 0) c[w] = p;
        }
    } else {
        int i = (blockIdx.x - 1) * blockDim.x + threadIdx.x;
        if (i < n) {
            int cc = cnt[i];
            la[i] = (cc > 0) ? (sumw[i] / (float)cc) : 0.0f;
        }
    }
}

// ---------------- aggregation: per-dst softmax + weighted gather --------------
__device__ __forceinline__ float lrelu(float a) { return a > 0.f ? a : 0.2f * a; }

template <int F, bool EDGE, bool RELU>
__global__ void k_aggregate(const float* __restrict__ xl, const float* __restrict__ asrc,
                            const float* __restrict__ adst, const int* __restrict__ ptr,
                            const int* __restrict__ csrc, const float* __restrict__ csw,
                            const float* __restrict__ la, const float* __restrict__ cvec,
                            int cidx, const float* __restrict__ bias,
                            float* __restrict__ out, int n) {
    constexpr int CPL = F / 32;   // 4 for F=128, 2 for F=64
    int wid = (blockIdx.x * blockDim.x + threadIdx.x) >> 5;
    int lane = threadIdx.x & 31;
    if (wid >= n) return;
    int v = wid;

    float c = EDGE ? cvec[cidx] : 0.f;
    float adv = adst[v];

    float a0 = asrc[v] + adv;
    if (EDGE) a0 += la[v] * c;
    a0 = lrelu(a0);
    float m = a0, den = 1.0f;

    float acc[CPL];
    {
        const float* row = xl + (size_t)v * F;
        if constexpr (CPL == 4) {
            float4 t = ((const float4*)row)[lane];
            acc[0] = t.x; acc[1] = t.y; acc[2] = t.z; acc[3] = t.w;
        } else {
            float2 t = ((const float2*)row)[lane];
            acc[0] = t.x; acc[1] = t.y;
        }
    }

    int rs = ptr[v], re = ptr[v + 1];
    for (int b = rs; b < re; b += 32) {
        int e = b + lane;
        float al = 0.f;
        int sIdx = 0;
        if (e < re) {
            sIdx = csrc[e];
            float a = asrc[sIdx] + adv;
            if (EDGE) a += csw[e] * c;
            al = lrelu(a);
        }
        int cnt = min(32, re - b);
        for (int j = 0; j < cnt; j++) {
            float a = __shfl_sync(0xffffffffu, al, j);
            int s = __shfl_sync(0xffffffffu, sIdx, j);
            float w;
            if (a > m) {           // warp-uniform branch
                float r = __expf(m - a);
                den *= r;
#pragma unroll
                for (int i = 0; i < CPL; i++) acc[i] *= r;
                m = a;
                w = 1.0f;
            } else {
                w = __expf(a - m);
            }
            den += w;
            const float* srow = xl + (size_t)s * F;
            if constexpr (CPL == 4) {
                float4 t = ((const float4*)srow)[lane];
                acc[0] += w * t.x; acc[1] += w * t.y;
                acc[2] += w * t.z; acc[3] += w * t.w;
            } else {
                float2 t = ((const float2*)srow)[lane];
                acc[0] += w * t.x; acc[1] += w * t.y;
            }
        }
    }

    float inv = 1.0f / den;
    if constexpr (CPL == 4) {
        float4 bv = ((const float4*)bias)[lane];
        float4 o;
        o.x = acc[0] * inv + bv.x;
        o.y = acc[1] * inv + bv.y;
        o.z = acc[2] * inv + bv.z;
        o.w = acc[3] * inv + bv.w;
        if (RELU) {
            o.x = fmaxf(o.x, 0.f); o.y = fmaxf(o.y, 0.f);
            o.z = fmaxf(o.z, 0.f); o.w = fmaxf(o.w, 0.f);
        }
        ((float4*)(out + (size_t)v * F))[lane] = o;
    } else {
        float2 bv = ((const float2*)bias)[lane];
        float2 o;
        o.x = acc[0] * inv + bv.x;
        o.y = acc[1] * inv + bv.y;
        if (RELU) { o.x = fmaxf(o.x, 0.f); o.y = fmaxf(o.y, 0.f); }
        ((float2*)(out + (size_t)v * F))[lane] = o;
    }
}

// ---------------- launch ------------------------------------------------------
extern "C" void kernel_launch(void* const* d_in, const int* in_sizes, int n_in,
                              void* d_out, int out_size) {
    const float* x      = (const float*)d_in[0];
    const void*  ei_raw = d_in[1];          // int32 or int64, probed at runtime
    const float* ew     = (const float*)d_in[2];
    const float *W0 = (const float*)d_in[3],  *as0 = (const float*)d_in[4],
                *ad0 = (const float*)d_in[5], *ae0 = (const float*)d_in[6],
                *We0 = (const float*)d_in[7], *b0  = (const float*)d_in[8];
    const float *W1 = (const float*)d_in[9],  *as1 = (const float*)d_in[10],
                *ad1 = (const float*)d_in[11], *ae1 = (const float*)d_in[12],
                *We1 = (const float*)d_in[13], *b1  = (const float*)d_in[14];
    const float *Wm = (const float*)d_in[15], *asm_ = (const float*)d_in[16],
                *adm = (const float*)d_in[17], *aem = (const float*)d_in[18],
                *Wem = (const float*)d_in[19], *bm  = (const float*)d_in[20];
    const float *Wl = (const float*)d_in[21], *asl = (const float*)d_in[22],
                *adl = (const float*)d_in[23], *bl  = (const float*)d_in[24];
    float* out = (float*)d_out;

    int *p_flag, *p_src, *p_dst, *p_cnt, *p_fill, *p_ptr, *p_bsum, *p_csrc;
    float *p_csw, *p_sumw, *p_loop, *p_xl, *p_h, *p_asrc, *p_adst, *p_c;
    __nv_bfloat16 *p_bh, *p_bl, *p_wh, *p_wl;
    cudaGetSymbolAddress((void**)&p_flag, g_flag64);
    cudaGetSymbolAddress((void**)&p_src,  g_src);
    cudaGetSymbolAddress((void**)&p_dst,  g_dst);
    cudaGetSymbolAddress((void**)&p_cnt,  g_cnt);
    cudaGetSymbolAddress((void**)&p_fill, g_fill);
    cudaGetSymbolAddress((void**)&p_ptr,  g_ptr);
    cudaGetSymbolAddress((void**)&p_bsum, g_bsum);
    cudaGetSymbolAddress((void**)&p_csrc, g_csrc);
    cudaGetSymbolAddress((void**)&p_csw,  g_csw);
    cudaGetSymbolAddress((void**)&p_sumw, g_sumw);
    cudaGetSymbolAddress((void**)&p_loop, g_loop);
    cudaGetSymbolAddress((void**)&p_xl,   g_xl);
    cudaGetSymbolAddress((void**)&p_h,    g_h);
    cudaGetSymbolAddress((void**)&p_asrc, g_asrc);
    cudaGetSymbolAddress((void**)&p_adst, g_adst);
    cudaGetSymbolAddress((void**)&p_c,    g_c);
    cudaGetSymbolAddress((void**)&p_bh,   g_bh);
    cudaGetSymbolAddress((void**)&p_bl,   g_bl);
    cudaGetSymbolAddress((void**)&p_wh,   g_wh);
    cudaGetSymbolAddress((void**)&p_wl,   g_wl);

    // smem: 2 W halves + 2 A bufs x 2 halves + attention vecs
    const int sm128 = 2 * (128 * 272) + 4 * (128 * 272) + 2 * 128 * 4;  // 209920... wait
    const int sm64  = 2 * (64 * 272)  + 4 * (128 * 272) + 2 * 64 * 4;
    cudaFuncSetAttribute(k_mma<128>, cudaFuncAttributeMaxDynamicSharedMemorySize, sm128);
    cudaFuncSetAttribute(k_mma<64>,  cudaFuncAttributeMaxDynamicSharedMemorySize, sm64);

    const int agg_blocks = (NN + 7) / 8;     // 8 warps/block, warp per node
    const int cx_blocks  = (NN * 128 / 4 + 255) / 256;

    // 1: weight transpose + bf16 split
    k_convw<<<(49152 + 255) / 256, 256>>>(W0, W1, Wm, Wl, p_wh, p_wl);
    // 2: split input x
    k_convx<<<cx_blocks, 256>>>(x, p_bh, p_bl, NN * 128 / 4);
    // 3: zero scratch
    k_zero<<<(NN + 255) / 256, 256>>>(p_cnt, p_fill, p_sumw, NN);
    // 4: layer-0 GEMM (tensor cores; 4th launch for the profiled slot)
    k_mma<128><<<MMA_GRID, 256, sm128>>>(p_bh, p_bl, p_wh, p_wl, as0, ad0,
                                         p_xl, p_asrc, p_adst, NN, NTILES);
    // 5-10: CSR build
    k_probe<<<1, 256>>>(ei_raw, p_flag);
    k_convert<<<(NE + 255) / 256, 256>>>(ei_raw, p_flag, p_src, p_dst, p_cnt, NE);
    k_scan1<<<NB_SCAN, SCAN_B>>>(p_cnt, p_ptr, p_bsum, NN);
    k_scan23<<<NB_SCAN, SCAN_B>>>(p_ptr, p_bsum, NN);
    k_scatter<<<(NE + 255) / 256, 256>>>(p_src, p_dst, ew, p_ptr, p_fill,
                                         p_csrc, p_csw, p_sumw, NE);
    k_misc<<<1 + (NN + 255) / 256, 256>>>(p_cnt, p_sumw, p_loop,
                                          We0, ae0, We1, ae1, Wem, aem, p_c, NN);

    // layer 0 aggregate (relu)
    k_aggregate<128, true, true><<<agg_blocks, 256>>>(p_xl, p_asrc, p_adst, p_ptr, p_csrc,
                                                      p_csw, p_loop, p_c, 0, b0, p_h, NN);
    // layer 1
    k_convx<<<cx_blocks, 256>>>(p_h, p_bh, p_bl, NN * 128 / 4);
    k_mma<128><<<MMA_GRID, 256, sm128>>>(p_bh, p_bl, p_wh + 16384, p_wl + 16384, as1, ad1,
                                         p_xl, p_asrc, p_adst, NN, NTILES);
    k_aggregate<128, true, true><<<agg_blocks, 256>>>(p_xl, p_asrc, p_adst, p_ptr, p_csrc,
                                                      p_csw, p_loop, p_c, 1, b1, p_h, NN);
    // mu
    k_convx<<<cx_blocks, 256>>>(p_h, p_bh, p_bl, NN * 128 / 4);
    k_mma<64><<<MMA_GRID, 256, sm64>>>(p_bh, p_bl, p_wh + 32768, p_wl + 32768, asm_, adm,
                                       p_xl, p_asrc, p_adst, NN, NTILES);
    k_aggregate<64, true, false><<<agg_blocks, 256>>>(p_xl, p_asrc, p_adst, p_ptr, p_csrc,
                                                      p_csw, p_loop, p_c, 2, bm, out, NN);
    // logstd (no edge term)
    k_mma<64><<<MMA_GRID, 256, sm64>>>(p_bh, p_bl, p_wh + 40960, p_wl + 40960, asl, adl,
                                       p_xl, p_asrc, p_adst, NN, NTILES);
    k_aggregate<64, false, false><<<agg_blocks, 256>>>(p_xl, p_asrc, p_adst, p_ptr, p_csrc,
                                                       p_csw, p_loop, p_c, 0, bl,
                                                       out + (size_t)NN * 64, NN);
}

// round 6
// speedup vs baseline: 1.5820x; 1.0724x over previous
#include <cuda_runtime.h>
#include <cuda_bf16.h>
#include <cstdint>

// Problem constants (fixed by the dataset)
#define NN 100000
#define NE 1600000
#define SCAN_B 1024
#define NB_SCAN ((NN + SCAN_B - 1) / SCAN_B)   // 98
#define NTILES ((NN + 127) / 128)              // 782
#define MMA_GRID 148

// ---------------- scratch (device globals; no allocation allowed) -------------
__device__ int   g_flag64;           // 1 if edge_index buffer is int64
__device__ int   g_src[NE];
__device__ int   g_dst[NE];
__device__ int   g_cnt[NN];
__device__ int   g_fill[NN];
__device__ int   g_ptr[NN + 1];
__device__ int   g_bsum[128];
__device__ int   g_csrc[NE];
__device__ float g_csw[NE];
__device__ float g_sumw[NN];
__device__ float g_loop[NN];
__device__ float g_xl[(size_t)NN * 128];
__device__ float g_h[(size_t)NN * 128];
__device__ float g_asrc[NN];
__device__ float g_adst[NN];
__device__ float g_c[4];
__device__ __nv_bfloat16 g_bh[(size_t)NN * 128];
__device__ __nv_bfloat16 g_bl[(size_t)NN * 128];
__device__ __nv_bfloat16 g_wh[49152];
__device__ __nv_bfloat16 g_wl[49152];

// ---------------- helpers -------------------------------------------------------
__device__ __forceinline__ uint32_t s2u(const void* p) {
    uint32_t a;
    asm("{ .reg .u64 t; cvta.to.shared.u64 t, %1; cvt.u32.u64 %0, t; }"
        : "=r"(a) : "l"(p));
    return a;
}
__device__ __forceinline__ void cp16(uint32_t saddr, const void* g, int sz) {
    asm volatile("cp.async.cg.shared.global [%0], [%1], 16, %2;"
                 :: "r"(saddr), "l"(g), "r"(sz));
}
__device__ __forceinline__ void cp_commit() {
    asm volatile("cp.async.commit_group;" ::: "memory");
}
__device__ __forceinline__ void cp_wait1() {
    asm volatile("cp.async.wait_group 1;" ::: "memory");
}
__device__ __forceinline__ void cp_wait0() {
    asm volatile("cp.async.wait_group 0;" ::: "memory");
}
__device__ __forceinline__ void ldsm4(uint32_t* r, uint32_t addr) {
    asm volatile("ldmatrix.sync.aligned.m8n8.x4.shared.b16 {%0,%1,%2,%3}, [%4];"
                 : "=r"(r[0]), "=r"(r[1]), "=r"(r[2]), "=r"(r[3]) : "r"(addr));
}
__device__ __forceinline__ void mma16816(float* d, const uint32_t* a, const uint32_t* b) {
    asm volatile(
        "mma.sync.aligned.m16n8k16.row.col.f32.bf16.bf16.f32 "
        "{%0,%1,%2,%3}, {%4,%5,%6,%7}, {%8,%9}, {%0,%1,%2,%3};"
        : "+f"(d[0]), "+f"(d[1]), "+f"(d[2]), "+f"(d[3])
        : "r"(a[0]), "r"(a[1]), "r"(a[2]), "r"(a[3]), "r"(b[0]), "r"(b[1]));
}

// async-load a [ROWS x 128] bf16 K-major tile into smem with padded row stride
// 136 bf16 (272 bytes): conflict-free for ldmatrix (rows shift by 4 banks).
template <int ROWS, int NTHR>
__device__ __forceinline__ void load_tile(uint32_t sbase, const __nv_bfloat16* src,
                                          size_t row0, int nrows, int tid) {
#pragma unroll 4
    for (int c = tid; c < ROWS * 16; c += NTHR) {
        int row = c >> 4, kc = c & 15;
        uint32_t off = (uint32_t)row * 272 + kc * 16;
        size_t grow = (row < nrows) ? (row0 + row) : row0;
        cp16(sbase + off, src + grow * 128 + kc * 8, (row < nrows) ? 16 : 0);
    }
}

// ---------------- GEMM via mma.sync bf16x3 split --------------------------------
// Y[n, NOUT] = X[n,128] @ W[128,NOUT]; X = Ah+Al (bf16 hi/lo), Wt = Bh+Bl
// stored [NOUT][128] K-major. 3 passes AhBh + AhBl + AlBh, fp32 accumulate.
// Fused epilogue: per-row attention dots asrc = y.a_s, adst = y.a_d.
template <int NOUT>
__global__ void __launch_bounds__(256, 1)
k_mma(const __nv_bfloat16* __restrict__ Ah, const __nv_bfloat16* __restrict__ Al,
      const __nv_bfloat16* __restrict__ Bh, const __nv_bfloat16* __restrict__ Bl,
      const float* __restrict__ a_s, const float* __restrict__ a_d,
      float* __restrict__ Y, float* __restrict__ asrc, float* __restrict__ adst,
      int n, int ntiles) {
    constexpr int NT = NOUT / 8;               // n-tiles (16 or 8)
    constexpr int WB = NOUT * 272;             // bytes per W split half
    constexpr int AB = 128 * 272;              // bytes per A split half (34816)
    extern __shared__ __align__(16) char smem[];
    char* sWh = smem;
    char* sWl = smem + WB;
    char* sA  = smem + 2 * WB;                 // 2 bufs x (Ah | Al)
    float* sAtt = (float*)(smem + 2 * WB + 4 * AB);

    int tid = threadIdx.x, warp = tid >> 5, lane = tid & 31;

    for (int i = tid; i < NOUT; i += 256) { sAtt[i] = a_s[i]; sAtt[NOUT + i] = a_d[i]; }

    uint32_t uWh = s2u(sWh), uWl = s2u(sWl), uA = s2u(sA);

    // prologue: W (hi+lo), then A tile 0
    load_tile<NOUT, 256>(uWh, Bh, 0, NOUT, tid);
    load_tile<NOUT, 256>(uWl, Bl, 0, NOUT, tid);
    cp_commit();
    {
        int t0 = blockIdx.x;
        int nr = min(128, n - t0 * 128);
        load_tile<128, 256>(uA, Ah, (size_t)t0 * 128, nr, tid);
        load_tile<128, 256>(uA + AB, Al, (size_t)t0 * 128, nr, tid);
        cp_commit();
    }

    // ldmatrix address offsets (within a split half)
    int mi = lane >> 3, l7 = lane & 7;
    uint32_t aoff = (uint32_t)(warp * 16 + ((mi & 1) << 3) + l7) * 272 + ((mi >> 1) << 3) * 2;
    uint32_t boff = (uint32_t)(((mi >> 1) << 3) + l7) * 272 + ((mi & 1) << 3) * 2;

    int buf = 0;
    for (int t = blockIdx.x; t < ntiles; t += gridDim.x) {
        int tn = t + gridDim.x;
        if (tn < ntiles) {
            int nr = min(128, n - tn * 128);
            uint32_t nb = uA + (buf ^ 1) * 2 * AB;
            load_tile<128, 256>(nb, Ah, (size_t)tn * 128, nr, tid);
            load_tile<128, 256>(nb + AB, Al, (size_t)tn * 128, nr, tid);
            cp_commit();
            cp_wait1();
        } else {
            cp_wait0();
        }
        __syncthreads();

        uint32_t uAh = uA + buf * 2 * AB;
        uint32_t uAl = uAh + AB;

        float acc[NT][4];
#pragma unroll
        for (int j = 0; j < NT; j++)
#pragma unroll
            for (int q = 0; q < 4; q++) acc[j][q] = 0.f;

#pragma unroll
        for (int ks = 0; ks < 8; ks++) {
            uint32_t kb = ks * 32;   // 16 bf16 = 32 bytes per k-step
            uint32_t ah[4], al_[4];
            ldsm4(ah, uAh + aoff + kb);
            ldsm4(al_, uAl + aoff + kb);
#pragma unroll
            for (int j = 0; j < NT; j += 2) {
                uint32_t bh[4], bl_[4];
                uint32_t bo = boff + (uint32_t)j * 8 * 272 + kb;
                ldsm4(bh, uWh + bo);
                ldsm4(bl_, uWl + bo);
                mma16816(acc[j],     ah,  bh);
                mma16816(acc[j + 1], ah,  bh + 2);
                mma16816(acc[j],     ah,  bl_);
                mma16816(acc[j + 1], ah,  bl_ + 2);
                mma16816(acc[j],     al_, bh);
                mma16816(acc[j + 1], al_, bh + 2);
            }
        }

        // epilogue: C frag (r0=row l/4, r1=row+8; cols j*8 + 2*(l%4))
        int r0 = warp * 16 + (lane >> 2);
        int node0 = t * 128 + r0;
        int node1 = node0 + 8;
        bool v0 = node0 < n, v1 = node1 < n;
        float pa0 = 0.f, pd0 = 0.f, pa1 = 0.f, pd1 = 0.f;
        int cb = (lane & 3) * 2;
#pragma unroll
        for (int j = 0; j < NT; j++) {
            int c = j * 8 + cb;
            float s0 = sAtt[c], s1 = sAtt[c + 1];
            float d0 = sAtt[NOUT + c], d1 = sAtt[NOUT + c + 1];
            pa0 += acc[j][0] * s0 + acc[j][1] * s1;
            pd0 += acc[j][0] * d0 + acc[j][1] * d1;
            pa1 += acc[j][2] * s0 + acc[j][3] * s1;
            pd1 += acc[j][2] * d0 + acc[j][3] * d1;
            if (v0) *(float2*)(Y + (size_t)node0 * NOUT + c) = make_float2(acc[j][0], acc[j][1]);
            if (v1) *(float2*)(Y + (size_t)node1 * NOUT + c) = make_float2(acc[j][2], acc[j][3]);
        }
#pragma unroll
        for (int o = 1; o <= 2; o <<= 1) {
            pa0 += __shfl_xor_sync(0xffffffffu, pa0, o);
            pd0 += __shfl_xor_sync(0xffffffffu, pd0, o);
            pa1 += __shfl_xor_sync(0xffffffffu, pa1, o);
            pd1 += __shfl_xor_sync(0xffffffffu, pd1, o);
        }
        if ((lane & 3) == 0) {
            if (v0) { asrc[node0] = pa0; adst[node0] = pd0; }
            if (v1) { asrc[node1] = pa1; adst[node1] = pd1; }
        }
        __syncthreads();
        buf ^= 1;
    }
}

// ---------------- fp32 -> bf16 hi/lo split -------------------------------------
__global__ void k_convx(const float* __restrict__ s, __nv_bfloat16* __restrict__ bh,
                        __nv_bfloat16* __restrict__ bl, int n4) {
    int i = blockIdx.x * blockDim.x + threadIdx.x;
    if (i >= n4) return;
    float4 v = ((const float4*)s)[i];
    __nv_bfloat16 h0 = __float2bfloat16(v.x), h1 = __float2bfloat16(v.y);
    __nv_bfloat16 h2 = __float2bfloat16(v.z), h3 = __float2bfloat16(v.w);
    __nv_bfloat16 l0 = __float2bfloat16(v.x - __bfloat162float(h0));
    __nv_bfloat16 l1 = __float2bfloat16(v.y - __bfloat162float(h1));
    __nv_bfloat16 l2 = __float2bfloat16(v.z - __bfloat162float(h2));
    __nv_bfloat16 l3 = __float2bfloat16(v.w - __bfloat162float(h3));
    ((__nv_bfloat162*)bh)[i * 2]     = __nv_bfloat162(h0, h1);
    ((__nv_bfloat162*)bh)[i * 2 + 1] = __nv_bfloat162(h2, h3);
    ((__nv_bfloat162*)bl)[i * 2]     = __nv_bfloat162(l0, l1);
    ((__nv_bfloat162*)bl)[i * 2 + 1] = __nv_bfloat162(l2, l3);
}

// transpose + split all 4 weight matrices into wt[n*128+k] hi/lo
// offsets: W0t=0, W1t=16384, Wmt=32768, Wlt=40960 (total 49152)
__global__ void k_convw(const float* __restrict__ W0, const float* __restrict__ W1,
                        const float* __restrict__ Wm, const float* __restrict__ Wl,
                        __nv_bfloat16* __restrict__ wh, __nv_bfloat16* __restrict__ wl_) {
    int i = blockIdx.x * blockDim.x + threadIdx.x;
    if (i >= 49152) return;
    float v;
    if (i < 16384)      { int j = i;         int nn = j >> 7, k = j & 127; v = W0[k * 128 + nn]; }
    else if (i < 32768) { int j = i - 16384; int nn = j >> 7, k = j & 127; v = W1[k * 128 + nn]; }
    else if (i < 40960) { int j = i - 32768; int nn = j >> 7, k = j & 127; v = Wm[k * 64 + nn]; }
    else                { int j = i - 40960; int nn = j >> 7, k = j & 127; v = Wl[k * 64 + nn]; }
    __nv_bfloat16 h = __float2bfloat16(v);
    wh[i] = h;
    wl_[i] = __float2bfloat16(v - __bfloat162float(h));
}

// ---------------- zero scratch -------------------------------------------------
__global__ void k_zero(int* __restrict__ cnt, int* __restrict__ fill,
                       float* __restrict__ sumw, int n) {
    int i = blockIdx.x * blockDim.x + threadIdx.x;
    if (i < n) { cnt[i] = 0; fill[i] = 0; sumw[i] = 0.f; }
}

// ---------------- dtype probe --------------------------------------------------
__global__ void k_probe(const void* __restrict__ ei_raw, int* __restrict__ flag) {
    __shared__ int bad;
    if (threadIdx.x == 0) bad = 0;
    __syncthreads();
    const long long* p = (const long long*)ei_raw;
    for (int i = threadIdx.x; i < 4096; i += blockDim.x) {
        long long v = p[i];
        if (v < 0 || v >= (long long)NN) bad = 1;
    }
    __syncthreads();
    if (threadIdx.x == 0) *flag = bad ? 0 : 1;
}

__global__ void k_convert(const void* __restrict__ ei_raw, const int* __restrict__ flag,
                          int* __restrict__ src, int* __restrict__ dst,
                          int* __restrict__ cnt, int E) {
    int e = blockIdx.x * blockDim.x + threadIdx.x;
    if (e >= E) return;
    int s, d;
    if (__ldg(flag)) {
        const long long* p = (const long long*)ei_raw;
        s = (int)p[e]; d = (int)p[E + e];
    } else {
        const int* p = (const int*)ei_raw;
        s = p[e]; d = p[E + e];
    }
    src[e] = s; dst[e] = d;
    atomicAdd(&cnt[d], 1);
}

// ---------------- CSR build ---------------------------------------------------
__global__ void k_scan1(const int* __restrict__ cnt, int* __restrict__ ptr,
                        int* __restrict__ bsum, int n) {
    __shared__ int sm[SCAN_B];
    int i = blockIdx.x * SCAN_B + threadIdx.x;
    int v = (i < n) ? cnt[i] : 0;
    sm[threadIdx.x] = v;
    __syncthreads();
    for (int off = 1; off < SCAN_B; off <<= 1) {
        int t = (threadIdx.x >= off) ? sm[threadIdx.x - off] : 0;
        __syncthreads();
        sm[threadIdx.x] += t;
        __syncthreads();
    }
    if (i < n) ptr[i + 1] = sm[threadIdx.x];
    if (threadIdx.x == SCAN_B - 1) bsum[blockIdx.x] = sm[SCAN_B - 1];
    if (i == 0) ptr[0] = 0;
}

__global__ void k_scan23(int* __restrict__ ptr, const int* __restrict__ bsum, int n) {
    __shared__ int sm[128];
    int t = threadIdx.x;
    if (t < 128) sm[t] = (t < (int)blockIdx.x && t < NB_SCAN) ? bsum[t] : 0;
    __syncthreads();
    for (int off = 64; off; off >>= 1) {
        if (t < off) sm[t] += sm[t + off];
        __syncthreads();
    }
    int offs = sm[0];
    int i = blockIdx.x * SCAN_B + t;
    if (i < n) ptr[i + 1] += offs;
}

__global__ void k_scatter(const int* __restrict__ src, const int* __restrict__ dst,
                          const float* __restrict__ ew,
                          const int* __restrict__ ptr, int* __restrict__ fill,
                          int* __restrict__ csrc, float* __restrict__ csw,
                          float* __restrict__ sumw, int E) {
    int e = blockIdx.x * blockDim.x + threadIdx.x;
    if (e >= E) return;
    int s = src[e];
    int d = dst[e];
    float w = ew[e];
    int pos = ptr[d] + atomicAdd(&fill[d], 1);
    csrc[pos] = s;
    csw[pos] = w;
    atomicAdd(&sumw[d], w);
}

// fused: 3 edge-attention dots (block 0) + self-loop attr (blocks 1..)
__global__ void k_misc(const int* __restrict__ cnt, const float* __restrict__ sumw,
                       float* __restrict__ la,
                       const float* __restrict__ We0, const float* __restrict__ ae0,
                       const float* __restrict__ We1, const float* __restrict__ ae1,
                       const float* __restrict__ Wem, const float* __restrict__ aem,
                       float* __restrict__ c, int n) {
    if (blockIdx.x == 0) {
        int w = threadIdx.x >> 5, lane = threadIdx.x & 31;
        if (w < 3) {
            const float* A = (w == 0) ? We0 : ((w == 1) ? We1 : Wem);
            const float* B = (w == 0) ? ae0 : ((w == 1) ? ae1 : aem);
            int len = (w == 2) ? 64 : 128;
            float p = 0.f;
            for (int i = lane; i < len; i += 32) p += A[i] * B[i];
#pragma unroll
            for (int off = 16; off; off >>= 1) p += __shfl_xor_sync(0xffffffffu, p, off);
            if (lane == 0) c[w] = p;
        }
    } else {
        int i = (blockIdx.x - 1) * blockDim.x + threadIdx.x;
        if (i < n) {
            int cc = cnt[i];
            la[i] = (cc > 0) ? (sumw[i] / (float)cc) : 0.0f;
        }
    }
}

// ---------------- aggregation: per-dst softmax + weighted gather --------------
// Two-pass exact max: pass A = warp-reduced max over edge logits (scalar loads),
// pass B = fixed-weight accumulation -> row gathers are independent (high MLP).
__device__ __forceinline__ float lrelu(float a) { return a > 0.f ? a : 0.2f * a; }

template <int F, bool EDGE, bool RELU, bool SPLIT>
__global__ void k_aggregate(const float* __restrict__ xl, const float* __restrict__ asrc,
                            const float* __restrict__ adst, const int* __restrict__ ptr,
                            const int* __restrict__ csrc, const float* __restrict__ csw,
                            const float* __restrict__ la, const float* __restrict__ cvec,
                            int cidx, const float* __restrict__ bias,
                            float* __restrict__ out,
                            __nv_bfloat16* __restrict__ obh, __nv_bfloat16* __restrict__ obl,
                            int n) {
    constexpr int CPL = F / 32;   // 4 for F=128, 2 for F=64
    int wid = (blockIdx.x * blockDim.x + threadIdx.x) >> 5;
    int lane = threadIdx.x & 31;
    if (wid >= n) return;
    int v = wid;

    float c = EDGE ? cvec[cidx] : 0.f;
    float adv = adst[v];

    float a0 = asrc[v] + adv;
    if (EDGE) a0 += la[v] * c;
    a0 = lrelu(a0);

    int rs = ptr[v], re = ptr[v + 1];

    // pass A: exact max over self-loop + incoming edges
    float m = a0;
    for (int e = rs + lane; e < re; e += 32) {
        int s = csrc[e];
        float a = asrc[s] + adv;
        if (EDGE) a += csw[e] * c;
        m = fmaxf(m, lrelu(a));
    }
#pragma unroll
    for (int o = 16; o; o >>= 1) m = fmaxf(m, __shfl_xor_sync(0xffffffffu, m, o));

    // pass B: weighted accumulation with fixed weights
    float w0 = __expf(a0 - m);
    float denp = (lane == 0) ? w0 : 0.f;

    float acc[CPL];
    {
        const float* row = xl + (size_t)v * F;
        if constexpr (CPL == 4) {
            float4 t = ((const float4*)row)[lane];
            acc[0] = w0 * t.x; acc[1] = w0 * t.y; acc[2] = w0 * t.z; acc[3] = w0 * t.w;
        } else {
            float2 t = ((const float2*)row)[lane];
            acc[0] = w0 * t.x; acc[1] = w0 * t.y;
        }
    }

    for (int b = rs; b < re; b += 32) {
        int e = b + lane;
        float w = 0.f;
        int sIdx = 0;
        if (e < re) {
            sIdx = csrc[e];
            float a = asrc[sIdx] + adv;
            if (EDGE) a += csw[e] * c;
            w = __expf(lrelu(a) - m);
        }
        denp += w;
        int cnt = min(32, re - b);
#pragma unroll 4
        for (int j = 0; j < cnt; j++) {
            float wj = __shfl_sync(0xffffffffu, w, j);
            int sj = __shfl_sync(0xffffffffu, sIdx, j);
            const float* srow = xl + (size_t)sj * F;
            if constexpr (CPL == 4) {
                float4 t = ((const float4*)srow)[lane];
                acc[0] += wj * t.x; acc[1] += wj * t.y;
                acc[2] += wj * t.z; acc[3] += wj * t.w;
            } else {
                float2 t = ((const float2*)srow)[lane];
                acc[0] += wj * t.x; acc[1] += wj * t.y;
            }
        }
    }

#pragma unroll
    for (int o = 16; o; o >>= 1) denp += __shfl_xor_sync(0xffffffffu, denp, o);
    float inv = 1.0f / denp;

    float o_[CPL];
    if constexpr (CPL == 4) {
        float4 bv = ((const float4*)bias)[lane];
        o_[0] = acc[0] * inv + bv.x; o_[1] = acc[1] * inv + bv.y;
        o_[2] = acc[2] * inv + bv.z; o_[3] = acc[3] * inv + bv.w;
    } else {
        float2 bv = ((const float2*)bias)[lane];
        o_[0] = acc[0] * inv + bv.x; o_[1] = acc[1] * inv + bv.y;
    }
    if (RELU) {
#pragma unroll
        for (int i = 0; i < CPL; i++) o_[i] = fmaxf(o_[i], 0.f);
    }
    if constexpr (CPL == 4) {
        ((float4*)(out + (size_t)v * F))[lane] = make_float4(o_[0], o_[1], o_[2], o_[3]);
    } else {
        ((float2*)(out + (size_t)v * F))[lane] = make_float2(o_[0], o_[1]);
    }
    if constexpr (SPLIT) {
        // bf16 hi/lo split fused into the epilogue (feeds next GEMM)
        __nv_bfloat16 h[CPL], l[CPL];
#pragma unroll
        for (int i = 0; i < CPL; i++) {
            h[i] = __float2bfloat16(o_[i]);
            l[i] = __float2bfloat16(o_[i] - __bfloat162float(h[i]));
        }
        __nv_bfloat162* ph = (__nv_bfloat162*)(obh + (size_t)v * F) + lane * (CPL / 2);
        __nv_bfloat162* pl = (__nv_bfloat162*)(obl + (size_t)v * F) + lane * (CPL / 2);
#pragma unroll
        for (int i = 0; i < CPL / 2; i++) {
            ph[i] = __nv_bfloat162(h[i * 2], h[i * 2 + 1]);
            pl[i] = __nv_bfloat162(l[i * 2], l[i * 2 + 1]);
        }
    }
}

// ---------------- launch ------------------------------------------------------
extern "C" void kernel_launch(void* const* d_in, const int* in_sizes, int n_in,
                              void* d_out, int out_size) {
    const float* x      = (const float*)d_in[0];
    const void*  ei_raw = d_in[1];          // int32 or int64, probed at runtime
    const float* ew     = (const float*)d_in[2];
    const float *W0 = (const float*)d_in[3],  *as0 = (const float*)d_in[4],
                *ad0 = (const float*)d_in[5], *ae0 = (const float*)d_in[6],
                *We0 = (const float*)d_in[7], *b0  = (const float*)d_in[8];
    const float *W1 = (const float*)d_in[9],  *as1 = (const float*)d_in[10],
                *ad1 = (const float*)d_in[11], *ae1 = (const float*)d_in[12],
                *We1 = (const float*)d_in[13], *b1  = (const float*)d_in[14];
    const float *Wm = (const float*)d_in[15], *asm_ = (const float*)d_in[16],
                *adm = (const float*)d_in[17], *aem = (const float*)d_in[18],
                *Wem = (const float*)d_in[19], *bm  = (const float*)d_in[20];
    const float *Wl = (const float*)d_in[21], *asl = (const float*)d_in[22],
                *adl = (const float*)d_in[23], *bl  = (const float*)d_in[24];
    float* out = (float*)d_out;

    int *p_flag, *p_src, *p_dst, *p_cnt, *p_fill, *p_ptr, *p_bsum, *p_csrc;
    float *p_csw, *p_sumw, *p_loop, *p_xl, *p_h, *p_asrc, *p_adst, *p_c;
    __nv_bfloat16 *p_bh, *p_bl, *p_wh, *p_wl;
    cudaGetSymbolAddress((void**)&p_flag, g_flag64);
    cudaGetSymbolAddress((void**)&p_src,  g_src);
    cudaGetSymbolAddress((void**)&p_dst,  g_dst);
    cudaGetSymbolAddress((void**)&p_cnt,  g_cnt);
    cudaGetSymbolAddress((void**)&p_fill, g_fill);
    cudaGetSymbolAddress((void**)&p_ptr,  g_ptr);
    cudaGetSymbolAddress((void**)&p_bsum, g_bsum);
    cudaGetSymbolAddress((void**)&p_csrc, g_csrc);
    cudaGetSymbolAddress((void**)&p_csw,  g_csw);
    cudaGetSymbolAddress((void**)&p_sumw, g_sumw);
    cudaGetSymbolAddress((void**)&p_loop, g_loop);
    cudaGetSymbolAddress((void**)&p_xl,   g_xl);
    cudaGetSymbolAddress((void**)&p_h,    g_h);
    cudaGetSymbolAddress((void**)&p_asrc, g_asrc);
    cudaGetSymbolAddress((void**)&p_adst, g_adst);
    cudaGetSymbolAddress((void**)&p_c,    g_c);
    cudaGetSymbolAddress((void**)&p_bh,   g_bh);
    cudaGetSymbolAddress((void**)&p_bl,   g_bl);
    cudaGetSymbolAddress((void**)&p_wh,   g_wh);
    cudaGetSymbolAddress((void**)&p_wl,   g_wl);

    // smem: 2 W halves + 2 A bufs x 2 halves + attention vecs
    const int sm128 = 2 * (128 * 272) + 4 * (128 * 272) + 2 * 128 * 4;
    const int sm64  = 2 * (64 * 272)  + 4 * (128 * 272) + 2 * 64 * 4;
    cudaFuncSetAttribute(k_mma<128>, cudaFuncAttributeMaxDynamicSharedMemorySize, sm128);
    cudaFuncSetAttribute(k_mma<64>,  cudaFuncAttributeMaxDynamicSharedMemorySize, sm64);

    const int agg_blocks = (NN + 7) / 8;     // 8 warps/block, warp per node
    const int cx_blocks  = (NN * 128 / 4 + 255) / 256;

    // 1: weight transpose + bf16 split
    k_convw<<<(49152 + 255) / 256, 256>>>(W0, W1, Wm, Wl, p_wh, p_wl);
    // 2: split input x
    k_convx<<<cx_blocks, 256>>>(x, p_bh, p_bl, NN * 128 / 4);
    // 3: zero scratch
    k_zero<<<(NN + 255) / 256, 256>>>(p_cnt, p_fill, p_sumw, NN);
    // 4: layer-0 GEMM (tensor cores; 4th launch for the profiled slot)
    k_mma<128><<<MMA_GRID, 256, sm128>>>(p_bh, p_bl, p_wh, p_wl, as0, ad0,
                                         p_xl, p_asrc, p_adst, NN, NTILES);
    // 5-10: CSR build
    k_probe<<<1, 256>>>(ei_raw, p_flag);
    k_convert<<<(NE + 255) / 256, 256>>>(ei_raw, p_flag, p_src, p_dst, p_cnt, NE);
    k_scan1<<<NB_SCAN, SCAN_B>>>(p_cnt, p_ptr, p_bsum, NN);
    k_scan23<<<NB_SCAN, SCAN_B>>>(p_ptr, p_bsum, NN);
    k_scatter<<<(NE + 255) / 256, 256>>>(p_src, p_dst, ew, p_ptr, p_fill,
                                         p_csrc, p_csw, p_sumw, NE);
    k_misc<<<1 + (NN + 255) / 256, 256>>>(p_cnt, p_sumw, p_loop,
                                          We0, ae0, We1, ae1, Wem, aem, p_c, NN);

    // layer 0 aggregate (relu, + bf16 split for layer-1 GEMM)
    k_aggregate<128, true, true, true><<<agg_blocks, 256>>>(
        p_xl, p_asrc, p_adst, p_ptr, p_csrc, p_csw, p_loop, p_c, 0, b0,
        p_h, p_bh, p_bl, NN);
    // layer 1
    k_mma<128><<<MMA_GRID, 256, sm128>>>(p_bh, p_bl, p_wh + 16384, p_wl + 16384, as1, ad1,
                                         p_xl, p_asrc, p_adst, NN, NTILES);
    k_aggregate<128, true, true, true><<<agg_blocks, 256>>>(
        p_xl, p_asrc, p_adst, p_ptr, p_csrc, p_csw, p_loop, p_c, 1, b1,
        p_h, p_bh, p_bl, NN);
    // mu
    k_mma<64><<<MMA_GRID, 256, sm64>>>(p_bh, p_bl, p_wh + 32768, p_wl + 32768, asm_, adm,
                                       p_xl, p_asrc, p_adst, NN, NTILES);
    k_aggregate<64, true, false, false><<<agg_blocks, 256>>>(
        p_xl, p_asrc, p_adst, p_ptr, p_csrc, p_csw, p_loop, p_c, 2, bm,
        out, nullptr, nullptr, NN);
    // logstd (no edge term)
    k_mma<64><<<MMA_GRID, 256, sm64>>>(p_bh, p_bl, p_wh + 40960, p_wl + 40960, asl, adl,
                                       p_xl, p_asrc, p_adst, NN, NTILES);
    k_aggregate<64, false, false, false><<<agg_blocks, 256>>>(
        p_xl, p_asrc, p_adst, p_ptr, p_csrc, p_csw, p_loop, p_c, 0, bl,
        out + (size_t)NN * 64, nullptr, nullptr, NN);
}

// round 8
// speedup vs baseline: 1.6869x; 1.0663x over previous
#include <cuda_runtime.h>
#include <cuda_bf16.h>
#include <cstdint>

// Problem constants (fixed by the dataset)
#define NN 100000
#define NE 1600000
#define SCAN_B 1024
#define NB_SCAN ((NN + SCAN_B - 1) / SCAN_B)   // 98
#define NTILES ((NN + 127) / 128)              // 782
#define MMA_GRID 148

// ---------------- scratch (device globals; no allocation allowed) -------------
__device__ int   g_flag64;           // 1 if edge_index buffer is int64
__device__ int   g_cnt[NN];
__device__ int   g_fill[NN];
__device__ int   g_ptr[NN + 1];
__device__ int   g_bsum[128];
__device__ int   g_csrc[NE];
__device__ float g_csw[NE];
__device__ float g_sumw[NN];
__device__ float g_loop[NN];
__device__ float g_xl[(size_t)NN * 128];
__device__ float g_asrc[NN];
__device__ float g_adst[NN];
__device__ float g_asrc2[NN];
__device__ float g_adst2[NN];
__device__ float g_c[4];
__device__ __nv_bfloat16 g_bh[(size_t)NN * 128];
__device__ __nv_bfloat16 g_bl[(size_t)NN * 128];
__device__ __nv_bfloat16 g_wh[49152];
__device__ __nv_bfloat16 g_wl[49152];

// ---------------- helpers -------------------------------------------------------
__device__ __forceinline__ uint32_t s2u(const void* p) {
    uint32_t a;
    asm("{ .reg .u64 t; cvta.to.shared.u64 t, %1; cvt.u32.u64 %0, t; }"
        : "=r"(a) : "l"(p));
    return a;
}
__device__ __forceinline__ void cp16(uint32_t saddr, const void* g, int sz) {
    asm volatile("cp.async.cg.shared.global [%0], [%1], 16, %2;"
                 :: "r"(saddr), "l"(g), "r"(sz));
}
__device__ __forceinline__ void cp_commit() {
    asm volatile("cp.async.commit_group;" ::: "memory");
}
__device__ __forceinline__ void cp_wait1() {
    asm volatile("cp.async.wait_group 1;" ::: "memory");
}
__device__ __forceinline__ void cp_wait0() {
    asm volatile("cp.async.wait_group 0;" ::: "memory");
}
__device__ __forceinline__ void ldsm4(uint32_t* r, uint32_t addr) {
    asm volatile("ldmatrix.sync.aligned.m8n8.x4.shared.b16 {%0,%1,%2,%3}, [%4];"
                 : "=r"(r[0]), "=r"(r[1]), "=r"(r[2]), "=r"(r[3]) : "r"(addr));
}
__device__ __forceinline__ void mma16816(float* d, const uint32_t* a, const uint32_t* b) {
    asm volatile(
        "mma.sync.aligned.m16n8k16.row.col.f32.bf16.bf16.f32 "
        "{%0,%1,%2,%3}, {%4,%5,%6,%7}, {%8,%9}, {%0,%1,%2,%3};"
        : "+f"(d[0]), "+f"(d[1]), "+f"(d[2]), "+f"(d[3])
        : "r"(a[0]), "r"(a[1]), "r"(a[2]), "r"(a[3]), "r"(b[0]), "r"(b[1]));
}

// async-load a [ROWS x 128] bf16 K-major tile into smem, padded stride 272B
template <int ROWS, int NTHR>
__device__ __forceinline__ void load_tile(uint32_t sbase, const __nv_bfloat16* src,
                                          size_t row0, int nrows, int tid) {
#pragma unroll 4
    for (int c = tid; c < ROWS * 16; c += NTHR) {
        int row = c >> 4, kc = c & 15;
        uint32_t off = (uint32_t)row * 272 + kc * 16;
        size_t grow = (row < nrows) ? (row0 + row) : row0;
        cp16(sbase + off, src + grow * 128 + kc * 8, (row < nrows) ? 16 : 0);
    }
}

// ---------------- GEMM via mma.sync bf16x3 split --------------------------------
// Y[n,128] = X[n,128] @ W[128,128]; 3 passes AhBh + AhBl + AlBh, fp32 accumulate.
// DUAL: W = [Wm_t ; Wl_t]; epilogue emits mu attention dots (cols 0-63) into
// asrc/adst and logstd dots (cols 64-127) into asrc2/adst2.
template <bool DUAL>
__global__ void __launch_bounds__(256, 1)
k_mma(const __nv_bfloat16* __restrict__ Ah, const __nv_bfloat16* __restrict__ Al,
      const __nv_bfloat16* __restrict__ Bh, const __nv_bfloat16* __restrict__ Bl,
      const float* __restrict__ a_s, const float* __restrict__ a_d,
      const float* __restrict__ a_s2, const float* __restrict__ a_d2,
      float* __restrict__ Y, float* __restrict__ asrc, float* __restrict__ adst,
      float* __restrict__ asrc2, float* __restrict__ adst2,
      int n, int ntiles) {
    constexpr int NOUT = 128;
    constexpr int NT = 16;                     // n-tiles
    constexpr int WB = NOUT * 272;             // bytes per W split half
    constexpr int AB = 128 * 272;              // bytes per A split half
    extern __shared__ __align__(16) char smem[];
    char* sWh = smem;
    char* sWl = smem + WB;
    char* sA  = smem + 2 * WB;                 // 2 bufs x (Ah | Al)
    float* sAtt = (float*)(smem + 2 * WB + 4 * AB);

    int tid = threadIdx.x, warp = tid >> 5, lane = tid & 31;

    if constexpr (DUAL) {
        for (int i = tid; i < 64; i += 256) {
            sAtt[i] = a_s[i]; sAtt[64 + i] = a_s2[i];
            sAtt[128 + i] = a_d[i]; sAtt[192 + i] = a_d2[i];
        }
    } else {
        for (int i = tid; i < NOUT; i += 256) { sAtt[i] = a_s[i]; sAtt[NOUT + i] = a_d[i]; }
    }

    uint32_t uWh = s2u(sWh), uWl = s2u(sWl), uA = s2u(sA);

    load_tile<NOUT, 256>(uWh, Bh, 0, NOUT, tid);
    load_tile<NOUT, 256>(uWl, Bl, 0, NOUT, tid);
    cp_commit();
    {
        int t0 = blockIdx.x;
        int nr = min(128, n - t0 * 128);
        load_tile<128, 256>(uA, Ah, (size_t)t0 * 128, nr, tid);
        load_tile<128, 256>(uA + AB, Al, (size_t)t0 * 128, nr, tid);
        cp_commit();
    }

    int mi = lane >> 3, l7 = lane & 7;
    uint32_t aoff = (uint32_t)(warp * 16 + ((mi & 1) << 3) + l7) * 272 + ((mi >> 1) << 3) * 2;
    uint32_t boff = (uint32_t)(((mi >> 1) << 3) + l7) * 272 + ((mi & 1) << 3) * 2;

    int buf = 0;
    for (int t = blockIdx.x; t < ntiles; t += gridDim.x) {
        int tn = t + gridDim.x;
        if (tn < ntiles) {
            int nr = min(128, n - tn * 128);
            uint32_t nb = uA + (buf ^ 1) * 2 * AB;
            load_tile<128, 256>(nb, Ah, (size_t)tn * 128, nr, tid);
            load_tile<128, 256>(nb + AB, Al, (size_t)tn * 128, nr, tid);
            cp_commit();
            cp_wait1();
        } else {
            cp_wait0();
        }
        __syncthreads();

        uint32_t uAh = uA + buf * 2 * AB;
        uint32_t uAl = uAh + AB;

        float acc[NT][4];
#pragma unroll
        for (int j = 0; j < NT; j++)
#pragma unroll
            for (int q = 0; q < 4; q++) acc[j][q] = 0.f;

#pragma unroll
        for (int ks = 0; ks < 8; ks++) {
            uint32_t kb = ks * 32;
            uint32_t ah[4], al_[4];
            ldsm4(ah, uAh + aoff + kb);
            ldsm4(al_, uAl + aoff + kb);
#pragma unroll
            for (int j = 0; j < NT; j += 2) {
                uint32_t bh[4], bl_[4];
                uint32_t bo = boff + (uint32_t)j * 8 * 272 + kb;
                ldsm4(bh, uWh + bo);
                ldsm4(bl_, uWl + bo);
                mma16816(acc[j],     ah,  bh);
                mma16816(acc[j + 1], ah,  bh + 2);
                mma16816(acc[j],     ah,  bl_);
                mma16816(acc[j + 1], ah,  bl_ + 2);
                mma16816(acc[j],     al_, bh);
                mma16816(acc[j + 1], al_, bh + 2);
            }
        }

        // epilogue
        int r0 = warp * 16 + (lane >> 2);
        int node0 = t * 128 + r0;
        int node1 = node0 + 8;
        bool v0 = node0 < n, v1 = node1 < n;
        float pa0 = 0.f, pd0 = 0.f, pa1 = 0.f, pd1 = 0.f;   // A-group (mu / full)
        float qa0 = 0.f, qd0 = 0.f, qa1 = 0.f, qd1 = 0.f;   // B-group (logstd, DUAL)
        int cb = (lane & 3) * 2;
#pragma unroll
        for (int j = 0; j < NT; j++) {
            int c = j * 8 + cb;
            float s0 = sAtt[c], s1 = sAtt[c + 1];
            float d0 = sAtt[NOUT + c], d1 = sAtt[NOUT + c + 1];
            if (DUAL && j >= NT / 2) {
                qa0 += acc[j][0] * s0 + acc[j][1] * s1;
                qd0 += acc[j][0] * d0 + acc[j][1] * d1;
                qa1 += acc[j][2] * s0 + acc[j][3] * s1;
                qd1 += acc[j][2] * d0 + acc[j][3] * d1;
            } else {
                pa0 += acc[j][0] * s0 + acc[j][1] * s1;
                pd0 += acc[j][0] * d0 + acc[j][1] * d1;
                pa1 += acc[j][2] * s0 + acc[j][3] * s1;
                pd1 += acc[j][2] * d0 + acc[j][3] * d1;
            }
            if (v0) *(float2*)(Y + (size_t)node0 * NOUT + c) = make_float2(acc[j][0], acc[j][1]);
            if (v1) *(float2*)(Y + (size_t)node1 * NOUT + c) = make_float2(acc[j][2], acc[j][3]);
        }
#pragma unroll
        for (int o = 1; o <= 2; o <<= 1) {
            pa0 += __shfl_xor_sync(0xffffffffu, pa0, o);
            pd0 += __shfl_xor_sync(0xffffffffu, pd0, o);
            pa1 += __shfl_xor_sync(0xffffffffu, pa1, o);
            pd1 += __shfl_xor_sync(0xffffffffu, pd1, o);
            if (DUAL) {
                qa0 += __shfl_xor_sync(0xffffffffu, qa0, o);
                qd0 += __shfl_xor_sync(0xffffffffu, qd0, o);
                qa1 += __shfl_xor_sync(0xffffffffu, qa1, o);
                qd1 += __shfl_xor_sync(0xffffffffu, qd1, o);
            }
        }
        if ((lane & 3) == 0) {
            if (v0) {
                asrc[node0] = pa0; adst[node0] = pd0;
                if (DUAL) { asrc2[node0] = qa0; adst2[node0] = qd0; }
            }
            if (v1) {
                asrc[node1] = pa1; adst[node1] = pd1;
                if (DUAL) { asrc2[node1] = qa1; adst2[node1] = qd1; }
            }
        }
        __syncthreads();
        buf ^= 1;
    }
}

// ---------------- fp32 -> bf16 hi/lo split -------------------------------------
__global__ void k_convx(const float* __restrict__ s, __nv_bfloat16* __restrict__ bh,
                        __nv_bfloat16* __restrict__ bl, int n4) {
    int i = blockIdx.x * blockDim.x + threadIdx.x;
    if (i >= n4) return;
    float4 v = ((const float4*)s)[i];
    __nv_bfloat16 h0 = __float2bfloat16(v.x), h1 = __float2bfloat16(v.y);
    __nv_bfloat16 h2 = __float2bfloat16(v.z), h3 = __float2bfloat16(v.w);
    __nv_bfloat16 l0 = __float2bfloat16(v.x - __bfloat162float(h0));
    __nv_bfloat16 l1 = __float2bfloat16(v.y - __bfloat162float(h1));
    __nv_bfloat16 l2 = __float2bfloat16(v.z - __bfloat162float(h2));
    __nv_bfloat16 l3 = __float2bfloat16(v.w - __bfloat162float(h3));
    ((__nv_bfloat162*)bh)[i * 2]     = __nv_bfloat162(h0, h1);
    ((__nv_bfloat162*)bh)[i * 2 + 1] = __nv_bfloat162(h2, h3);
    ((__nv_bfloat162*)bl)[i * 2]     = __nv_bfloat162(l0, l1);
    ((__nv_bfloat162*)bl)[i * 2 + 1] = __nv_bfloat162(l2, l3);
}

// transpose + split all 4 weight matrices into wt[n*128+k] hi/lo
// offsets: W0t=0, W1t=16384, Wmt=32768, Wlt=40960 (combined mu|logstd = 32768..49152)
__global__ void k_convw(const float* __restrict__ W0, const float* __restrict__ W1,
                        const float* __restrict__ Wm, const float* __restrict__ Wl,
                        __nv_bfloat16* __restrict__ wh, __nv_bfloat16* __restrict__ wl_) {
    int i = blockIdx.x * blockDim.x + threadIdx.x;
    if (i >= 49152) return;
    float v;
    if (i < 16384)      { int j = i;         int nn = j >> 7, k = j & 127; v = W0[k * 128 + nn]; }
    else if (i < 32768) { int j = i - 16384; int nn = j >> 7, k = j & 127; v = W1[k * 128 + nn]; }
    else if (i < 40960) { int j = i - 32768; int nn = j >> 7, k = j & 127; v = Wm[k * 64 + nn]; }
    else                { int j = i - 40960; int nn = j >> 7, k = j & 127; v = Wl[k * 64 + nn]; }
    __nv_bfloat16 h = __float2bfloat16(v);
    wh[i] = h;
    wl_[i] = __float2bfloat16(v - __bfloat162float(h));
}

// ---------------- zero scratch -------------------------------------------------
__global__ void k_zero(int* __restrict__ cnt, int* __restrict__ fill,
                       float* __restrict__ sumw, int n) {
    int i = blockIdx.x * blockDim.x + threadIdx.x;
    if (i < n) { cnt[i] = 0; fill[i] = 0; sumw[i] = 0.f; }
}

// ---------------- dtype probe --------------------------------------------------
__global__ void k_probe(const void* __restrict__ ei_raw, int* __restrict__ flag) {
    __shared__ int bad;
    if (threadIdx.x == 0) bad = 0;
    __syncthreads();
    const long long* p = (const long long*)ei_raw;
    for (int i = threadIdx.x; i < 4096; i += blockDim.x) {
        long long v = p[i];
        if (v < 0 || v >= (long long)NN) bad = 1;
    }
    __syncthreads();
    if (threadIdx.x == 0) *flag = bad ? 0 : 1;
}

// histogram of destination degrees (reads edge_index directly)
__global__ void k_hist(const void* __restrict__ ei_raw, const int* __restrict__ flag,
                       int* __restrict__ cnt, int E) {
    int e = blockIdx.x * blockDim.x + threadIdx.x;
    if (e >= E) return;
    int d;
    if (__ldg(flag)) d = (int)((const long long*)ei_raw)[E + e];
    else             d = ((const int*)ei_raw)[E + e];
    atomicAdd(&cnt[d], 1);
}

// ---------------- CSR build ---------------------------------------------------
__global__ void k_scan1(const int* __restrict__ cnt, int* __restrict__ ptr,
                        int* __restrict__ bsum, int n) {
    __shared__ int sm[SCAN_B];
    int i = blockIdx.x * SCAN_B + threadIdx.x;
    int v = (i < n) ? cnt[i] : 0;
    sm[threadIdx.x] = v;
    __syncthreads();
    for (int off = 1; off < SCAN_B; off <<= 1) {
        int t = (threadIdx.x >= off) ? sm[threadIdx.x - off] : 0;
        __syncthreads();
        sm[threadIdx.x] += t;
        __syncthreads();
    }
    if (i < n) ptr[i + 1] = sm[threadIdx.x];
    if (threadIdx.x == SCAN_B - 1) bsum[blockIdx.x] = sm[SCAN_B - 1];
    if (i == 0) ptr[0] = 0;
}

__global__ void k_scan23(int* __restrict__ ptr, const int* __restrict__ bsum, int n) {
    __shared__ int sm[128];
    int t = threadIdx.x;
    if (t < 128) sm[t] = (t < (int)blockIdx.x && t < NB_SCAN) ? bsum[t] : 0;
    __syncthreads();
    for (int off = 64; off; off >>= 1) {
        if (t < off) sm[t] += sm[t + off];
        __syncthreads();
    }
    int offs = sm[0];
    int i = blockIdx.x * SCAN_B + t;
    if (i < n) ptr[i + 1] += offs;
}

__global__ void k_scatter(const void* __restrict__ ei_raw, const int* __restrict__ flag,
                          const float* __restrict__ ew,
                          const int* __restrict__ ptr, int* __restrict__ fill,
                          int* __restrict__ csrc, float* __restrict__ csw,
                          float* __restrict__ sumw, int E) {
    int e = blockIdx.x * blockDim.x + threadIdx.x;
    if (e >= E) return;
    int s, d;
    if (__ldg(flag)) {
        const long long* p = (const long long*)ei_raw;
        s = (int)p[e]; d = (int)p[E + e];
    } else {
        const int* p = (const int*)ei_raw;
        s = p[e]; d = p[E + e];
    }
    float w = ew[e];
    int pos = ptr[d] + atomicAdd(&fill[d], 1);
    csrc[pos] = s;
    csw[pos] = w;
    atomicAdd(&sumw[d], w);
}

// fused: 3 edge-attention dots (block 0) + self-loop attr (blocks 1..)
__global__ void k_misc(const int* __restrict__ cnt, const float* __restrict__ sumw,
                       float* __restrict__ la,
                       const float* __restrict__ We0, const float* __restrict__ ae0,
                       const float* __restrict__ We1, const float* __restrict__ ae1,
                       const float* __restrict__ Wem, const float* __restrict__ aem,
                       float* __restrict__ c, int n) {
    if (blockIdx.x == 0) {
        int w = threadIdx.x >> 5, lane = threadIdx.x & 31;
        if (w < 3) {
            const float* A = (w == 0) ? We0 : ((w == 1) ? We1 : Wem);
            const float* B = (w == 0) ? ae0 : ((w == 1) ? ae1 : aem);
            int len = (w == 2) ? 64 : 128;
            float p = 0.f;
            for (int i = lane; i < len; i += 32) p += A[i] * B[i];
#pragma unroll
            for (int off = 16; off; off >>= 1) p += __shfl_xor_sync(0xffffffffu, p, off);
            if (lane == 0) c[w] = p;
        }
    } else {
        int i = (blockIdx.x - 1) * blockDim.x + threadIdx.x;
        if (i < n) {
            int cc = cnt[i];
            la[i] = (cc > 0) ? (sumw[i] / (float)cc) : 0.0f;
        }
    }
}

// ---------------- aggregation (layers 0/1): softmax gather, bf16-split output --
__device__ __forceinline__ float lrelu(float a) { return a > 0.f ? a : 0.2f * a; }

__global__ void k_aggregate(const float* __restrict__ xl, const float* __restrict__ asrc,
                            const float* __restrict__ adst, const int* __restrict__ ptr,
                            const int* __restrict__ csrc, const float* __restrict__ csw,
                            const float* __restrict__ la, const float* __restrict__ cvec,
                            int cidx, const float* __restrict__ bias,
                            __nv_bfloat16* __restrict__ obh, __nv_bfloat16* __restrict__ obl,
                            int n) {
    int wid = (blockIdx.x * blockDim.x + threadIdx.x) >> 5;
    int lane = threadIdx.x & 31;
    if (wid >= n) return;
    int v = wid;

    float c = cvec[cidx];
    float adv = adst[v];

    float a0 = lrelu(asrc[v] + adv + la[v] * c);
    int rs = ptr[v], re = ptr[v + 1];

    // pass A: exact max
    float m = a0;
    for (int e = rs + lane; e < re; e += 32)
        m = fmaxf(m, lrelu(asrc[csrc[e]] + adv + csw[e] * c));
#pragma unroll
    for (int o = 16; o; o >>= 1) m = fmaxf(m, __shfl_xor_sync(0xffffffffu, m, o));

    // pass B
    float w0 = __expf(a0 - m);
    float denp = (lane == 0) ? w0 : 0.f;
    float acc[4];
    {
        float4 t = ((const float4*)(xl + (size_t)v * 128))[lane];
        acc[0] = w0 * t.x; acc[1] = w0 * t.y; acc[2] = w0 * t.z; acc[3] = w0 * t.w;
    }
    for (int b = rs; b < re; b += 32) {
        int e = b + lane;
        float w = 0.f;
        int sIdx = 0;
        if (e < re) {
            sIdx = csrc[e];
            w = __expf(lrelu(asrc[sIdx] + adv + csw[e] * c) - m);
        }
        denp += w;
        int cnt = min(32, re - b);
#pragma unroll 4
        for (int j = 0; j < cnt; j++) {
            float wj = __shfl_sync(0xffffffffu, w, j);
            int sj = __shfl_sync(0xffffffffu, sIdx, j);
            float4 t = ((const float4*)(xl + (size_t)sj * 128))[lane];
            acc[0] += wj * t.x; acc[1] += wj * t.y;
            acc[2] += wj * t.z; acc[3] += wj * t.w;
        }
    }
#pragma unroll
    for (int o = 16; o; o >>= 1) denp += __shfl_xor_sync(0xffffffffu, denp, o);
    float inv = 1.0f / denp;

    float4 bv = ((const float4*)bias)[lane];
    float o_[4];
    o_[0] = fmaxf(acc[0] * inv + bv.x, 0.f);
    o_[1] = fmaxf(acc[1] * inv + bv.y, 0.f);
    o_[2] = fmaxf(acc[2] * inv + bv.z, 0.f);
    o_[3] = fmaxf(acc[3] * inv + bv.w, 0.f);

    __nv_bfloat16 h[4], l[4];
#pragma unroll
    for (int i = 0; i < 4; i++) {
        h[i] = __float2bfloat16(o_[i]);
        l[i] = __float2bfloat16(o_[i] - __bfloat162float(h[i]));
    }
    __nv_bfloat162* ph = (__nv_bfloat162*)(obh + (size_t)v * 128) + lane * 2;
    __nv_bfloat162* pl = (__nv_bfloat162*)(obl + (size_t)v * 128) + lane * 2;
    ph[0] = __nv_bfloat162(h[0], h[1]); ph[1] = __nv_bfloat162(h[2], h[3]);
    pl[0] = __nv_bfloat162(l[0], l[1]); pl[1] = __nv_bfloat162(l[2], l[3]);
}

// ---------------- fused mu+logstd aggregation ----------------------------------
// xl rows are [mu cols 0-63 | logstd cols 64-127]. Lanes 0-15 apply mu weights,
// lanes 16-31 logstd weights; one gather serves both heads.
__global__ void k_aggdual(const float* __restrict__ xl,
                          const float* __restrict__ asrcA, const float* __restrict__ adstA,
                          const float* __restrict__ asrcB, const float* __restrict__ adstB,
                          const int* __restrict__ ptr, const int* __restrict__ csrc,
                          const float* __restrict__ csw, const float* __restrict__ la,
                          const float* __restrict__ cvec,
                          const float* __restrict__ biasA, const float* __restrict__ biasB,
                          float* __restrict__ outA, float* __restrict__ outB, int n) {
    int wid = (blockIdx.x * blockDim.x + threadIdx.x) >> 5;
    int lane = threadIdx.x & 31;
    if (wid >= n) return;
    int v = wid;
    bool isA = lane < 16;

    float c = cvec[2];
    float advA = adstA[v], advB = adstB[v];
    float lav = la[v];

    float a0A = lrelu(asrcA[v] + advA + lav * c);
    float a0B = lrelu(asrcB[v] + advB);
    int rs = ptr[v], re = ptr[v + 1];

    float mA = a0A, mB = a0B;
    for (int e = rs + lane; e < re; e += 32) {
        int s = csrc[e];
        mA = fmaxf(mA, lrelu(asrcA[s] + advA + csw[e] * c));
        mB = fmaxf(mB, lrelu(asrcB[s] + advB));
    }
#pragma unroll
    for (int o = 16; o; o >>= 1) {
        mA = fmaxf(mA, __shfl_xor_sync(0xffffffffu, mA, o));
        mB = fmaxf(mB, __shfl_xor_sync(0xffffffffu, mB, o));
    }

    float w0A = __expf(a0A - mA), w0B = __expf(a0B - mB);
    float denA = (lane == 0) ? w0A : 0.f;
    float denB = (lane == 0) ? w0B : 0.f;
    float wsel0 = isA ? w0A : w0B;
    float acc[4];
    {
        float4 t = ((const float4*)(xl + (size_t)v * 128))[lane];
        acc[0] = wsel0 * t.x; acc[1] = wsel0 * t.y;
        acc[2] = wsel0 * t.z; acc[3] = wsel0 * t.w;
    }
    for (int b = rs; b < re; b += 32) {
        int e = b + lane;
        float wA = 0.f, wB = 0.f;
        int sIdx = 0;
        if (e < re) {
            sIdx = csrc[e];
            wA = __expf(lrelu(asrcA[sIdx] + advA + csw[e] * c) - mA);
            wB = __expf(lrelu(asrcB[sIdx] + advB) - mB);
        }
        denA += wA; denB += wB;
        int cnt = min(32, re - b);
#pragma unroll 4
        for (int j = 0; j < cnt; j++) {
            float wjA = __shfl_sync(0xffffffffu, wA, j);
            float wjB = __shfl_sync(0xffffffffu, wB, j);
            int sj = __shfl_sync(0xffffffffu, sIdx, j);
            float wj = isA ? wjA : wjB;
            float4 t = ((const float4*)(xl + (size_t)sj * 128))[lane];
            acc[0] += wj * t.x; acc[1] += wj * t.y;
            acc[2] += wj * t.z; acc[3] += wj * t.w;
        }
    }
#pragma unroll
    for (int o = 16; o; o >>= 1) {
        denA += __shfl_xor_sync(0xffffffffu, denA, o);
        denB += __shfl_xor_sync(0xffffffffu, denB, o);
    }
    float inv = isA ? (1.0f / denA) : (1.0f / denB);

    if (isA) {
        float4 bv = ((const float4*)biasA)[lane];
        ((float4*)(outA + (size_t)v * 64))[lane] =
            make_float4(acc[0] * inv + bv.x, acc[1] * inv + bv.y,
                        acc[2] * inv + bv.z, acc[3] * inv + bv.w);
    } else {
        float4 bv = ((const float4*)biasB)[lane - 16];
        ((float4*)(outB + (size_t)v * 64))[lane - 16] =
            make_float4(acc[0] * inv + bv.x, acc[1] * inv + bv.y,
                        acc[2] * inv + bv.z, acc[3] * inv + bv.w);
    }
}

// ---------------- launch ------------------------------------------------------
extern "C" void kernel_launch(void* const* d_in, const int* in_sizes, int n_in,
                              void* d_out, int out_size) {
    const float* x      = (const float*)d_in[0];
    const void*  ei_raw = d_in[1];          // int32 or int64, probed at runtime
    const float* ew     = (const float*)d_in[2];
    const float *W0 = (const float*)d_in[3],  *as0 = (const float*)d_in[4],
                *ad0 = (const float*)d_in[5], *ae0 = (const float*)d_in[6],
                *We0 = (const float*)d_in[7], *b0  = (const float*)d_in[8];
    const float *W1 = (const float*)d_in[9],  *as1 = (const float*)d_in[10],
                *ad1 = (const float*)d_in[11], *ae1 = (const float*)d_in[12],
                *We1 = (const float*)d_in[13], *b1  = (const float*)d_in[14];
    const float *Wm = (const float*)d_in[15], *asm_ = (const float*)d_in[16],
                *adm = (const float*)d_in[17], *aem = (const float*)d_in[18],
                *Wem = (const float*)d_in[19], *bm  = (const float*)d_in[20];
    const float *Wl = (const float*)d_in[21], *asl = (const float*)d_in[22],
                *adl = (const float*)d_in[23], *bl  = (const float*)d_in[24];
    float* out = (float*)d_out;

    int *p_flag, *p_cnt, *p_fill, *p_ptr, *p_bsum, *p_csrc;
    float *p_csw, *p_sumw, *p_loop, *p_xl, *p_asrc, *p_adst, *p_asrc2, *p_adst2, *p_c;
    __nv_bfloat16 *p_bh, *p_bl, *p_wh, *p_wl;
    cudaGetSymbolAddress((void**)&p_flag, g_flag64);
    cudaGetSymbolAddress((void**)&p_cnt,  g_cnt);
    cudaGetSymbolAddress((void**)&p_fill, g_fill);
    cudaGetSymbolAddress((void**)&p_ptr,  g_ptr);
    cudaGetSymbolAddress((void**)&p_bsum, g_bsum);
    cudaGetSymbolAddress((void**)&p_csrc, g_csrc);
    cudaGetSymbolAddress((void**)&p_csw,  g_csw);
    cudaGetSymbolAddress((void**)&p_sumw, g_sumw);
    cudaGetSymbolAddress((void**)&p_loop, g_loop);
    cudaGetSymbolAddress((void**)&p_xl,   g_xl);
    cudaGetSymbolAddress((void**)&p_asrc, g_asrc);
    cudaGetSymbolAddress((void**)&p_adst, g_adst);
    cudaGetSymbolAddress((void**)&p_asrc2, g_asrc2);
    cudaGetSymbolAddress((void**)&p_adst2, g_adst2);
    cudaGetSymbolAddress((void**)&p_c,    g_c);
    cudaGetSymbolAddress((void**)&p_bh,   g_bh);
    cudaGetSymbolAddress((void**)&p_bl,   g_bl);
    cudaGetSymbolAddress((void**)&p_wh,   g_wh);
    cudaGetSymbolAddress((void**)&p_wl,   g_wl);

    const int sm128 = 2 * (128 * 272) + 4 * (128 * 272) + 2 * 128 * 4;
    cudaFuncSetAttribute(k_mma<false>, cudaFuncAttributeMaxDynamicSharedMemorySize, sm128);
    cudaFuncSetAttribute(k_mma<true>,  cudaFuncAttributeMaxDynamicSharedMemorySize, sm128);

    const int agg_blocks = (NN + 7) / 8;     // 8 warps/block, warp per node
    const int cx_blocks  = (NN * 128 / 4 + 255) / 256;

    // 1: weight transpose + bf16 split
    k_convw<<<(49152 + 255) / 256, 256>>>(W0, W1, Wm, Wl, p_wh, p_wl);
    // 2: split input x
    k_convx<<<cx_blocks, 256>>>(x, p_bh, p_bl, NN * 128 / 4);
    // 3: zero scratch
    k_zero<<<(NN + 255) / 256, 256>>>(p_cnt, p_fill, p_sumw, NN);
    // 4: layer-0 GEMM (profiled slot)
    k_mma<false><<<MMA_GRID, 256, sm128>>>(p_bh, p_bl, p_wh, p_wl, as0, ad0,
                                           nullptr, nullptr, p_xl, p_asrc, p_adst,
                                           nullptr, nullptr, NN, NTILES);
    // 5-9: CSR build
    k_probe<<<1, 256>>>(ei_raw, p_flag);
    k_hist<<<(NE + 255) / 256, 256>>>(ei_raw, p_flag, p_cnt, NE);
    k_scan1<<<NB_SCAN, SCAN_B>>>(p_cnt, p_ptr, p_bsum, NN);
    k_scan23<<<NB_SCAN, SCAN_B>>>(p_ptr, p_bsum, NN);
    k_scatter<<<(NE + 255) / 256, 256>>>(ei_raw, p_flag, ew, p_ptr, p_fill,
                                         p_csrc, p_csw, p_sumw, NE);
    // 10: edge-attention scalars + self-loop attrs
    k_misc<<<1 + (NN + 255) / 256, 256>>>(p_cnt, p_sumw, p_loop,
                                          We0, ae0, We1, ae1, Wem, aem, p_c, NN);

    // layer 0 aggregate -> bf16 split
    k_aggregate<<<agg_blocks, 256>>>(p_xl, p_asrc, p_adst, p_ptr, p_csrc, p_csw,
                                     p_loop, p_c, 0, b0, p_bh, p_bl, NN);
    // layer 1
    k_mma<false><<<MMA_GRID, 256, sm128>>>(p_bh, p_bl, p_wh + 16384, p_wl + 16384, as1, ad1,
                                           nullptr, nullptr, p_xl, p_asrc, p_adst,
                                           nullptr, nullptr, NN, NTILES);
    k_aggregate<<<agg_blocks, 256>>>(p_xl, p_asrc, p_adst, p_ptr, p_csrc, p_csw,
                                     p_loop, p_c, 1, b1, p_bh, p_bl, NN);
    // mu+logstd fused GEMM (combined weights at offset 32768)
    k_mma<true><<<MMA_GRID, 256, sm128>>>(p_bh, p_bl, p_wh + 32768, p_wl + 32768,
                                          asm_, adm, asl, adl, p_xl,
                                          p_asrc, p_adst, p_asrc2, p_adst2, NN, NTILES);
    // fused mu+logstd aggregation
    k_aggdual<<<agg_blocks, 256>>>(p_xl, p_asrc, p_adst, p_asrc2, p_adst2,
                                   p_ptr, p_csrc, p_csw, p_loop, p_c,
                                   bm, bl, out, out + (size_t)NN * 64, NN);
}

// round 9
// speedup vs baseline: 1.8368x; 1.0888x over previous
#include <cuda_runtime.h>
#include <cuda_bf16.h>
#include <cuda_fp16.h>
#include <cstdint>

// Problem constants (fixed by the dataset)
#define NN 100000
#define NE 1600000
#define SCAN_B 1024
#define NB_SCAN ((NN + SCAN_B - 1) / SCAN_B)   // 98
#define NTILES ((NN + 127) / 128)              // 782
#define MMA_GRID 148

// ---------------- scratch (device globals; no allocation allowed) -------------
__device__ int   g_flag64;           // 1 if edge_index buffer is int64
__device__ int   g_cnt[NN];
__device__ int   g_fill[NN];
__device__ int   g_ptr[NN + 1];
__device__ int   g_bsum[128];
__device__ int   g_csrc[NE];
__device__ float g_csw[NE];
__device__ float g_sumw[NN];
__device__ float g_loop[NN];
__device__ float g_xl[(size_t)NN * 128];   // fp32 for DUAL; aliased as half for layers 0/1
__device__ float g_asrc[NN];
__device__ float g_adst[NN];
__device__ float g_asrc2[NN];
__device__ float g_adst2[NN];
__device__ float g_c[4];
__device__ __nv_bfloat16 g_bh[(size_t)NN * 128];
__device__ __nv_bfloat16 g_bl[(size_t)NN * 128];
__device__ __nv_bfloat16 g_wh[49152];
__device__ __nv_bfloat16 g_wl[49152];

// ---------------- helpers -------------------------------------------------------
__device__ __forceinline__ uint32_t s2u(const void* p) {
    uint32_t a;
    asm("{ .reg .u64 t; cvta.to.shared.u64 t, %1; cvt.u32.u64 %0, t; }"
        : "=r"(a) : "l"(p));
    return a;
}
__device__ __forceinline__ void cp16(uint32_t saddr, const void* g, int sz) {
    asm volatile("cp.async.cg.shared.global [%0], [%1], 16, %2;"
                 :: "r"(saddr), "l"(g), "r"(sz));
}
__device__ __forceinline__ void cp_commit() {
    asm volatile("cp.async.commit_group;" ::: "memory");
}
__device__ __forceinline__ void cp_wait1() {
    asm volatile("cp.async.wait_group 1;" ::: "memory");
}
__device__ __forceinline__ void cp_wait0() {
    asm volatile("cp.async.wait_group 0;" ::: "memory");
}
__device__ __forceinline__ void ldsm4(uint32_t* r, uint32_t addr) {
    asm volatile("ldmatrix.sync.aligned.m8n8.x4.shared.b16 {%0,%1,%2,%3}, [%4];"
                 : "=r"(r[0]), "=r"(r[1]), "=r"(r[2]), "=r"(r[3]) : "r"(addr));
}
__device__ __forceinline__ void mma16816(float* d, const uint32_t* a, const uint32_t* b) {
    asm volatile(
        "mma.sync.aligned.m16n8k16.row.col.f32.bf16.bf16.f32 "
        "{%0,%1,%2,%3}, {%4,%5,%6,%7}, {%8,%9}, {%0,%1,%2,%3};"
        : "+f"(d[0]), "+f"(d[1]), "+f"(d[2]), "+f"(d[3])
        : "r"(a[0]), "r"(a[1]), "r"(a[2]), "r"(a[3]), "r"(b[0]), "r"(b[1]));
}

// async-load a [ROWS x 128] bf16 K-major tile into smem, padded stride 272B
template <int ROWS, int NTHR>
__device__ __forceinline__ void load_tile(uint32_t sbase, const __nv_bfloat16* src,
                                          size_t row0, int nrows, int tid) {
#pragma unroll 4
    for (int c = tid; c < ROWS * 16; c += NTHR) {
        int row = c >> 4, kc = c & 15;
        uint32_t off = (uint32_t)row * 272 + kc * 16;
        size_t grow = (row < nrows) ? (row0 + row) : row0;
        cp16(sbase + off, src + grow * 128 + kc * 8, (row < nrows) ? 16 : 0);
    }
}

// ---------------- GEMM via mma.sync bf16x3 split --------------------------------
// Y[n,128] = X[n,128] @ W[128,128]; 3 passes AhBh + AhBl + AlBh, fp32 accumulate.
// DUAL=false: Y written as fp16 (feeds the bandwidth-bound aggregation gather).
// DUAL=true:  W = [Wm_t ; Wl_t]; Y written fp32; epilogue emits mu attention
//             dots (cols 0-63) into asrc/adst and logstd dots into asrc2/adst2.
template <bool DUAL>
__global__ void __launch_bounds__(256, 1)
k_mma(const __nv_bfloat16* __restrict__ Ah, const __nv_bfloat16* __restrict__ Al,
      const __nv_bfloat16* __restrict__ Bh, const __nv_bfloat16* __restrict__ Bl,
      const float* __restrict__ a_s, const float* __restrict__ a_d,
      const float* __restrict__ a_s2, const float* __restrict__ a_d2,
      float* __restrict__ Yf, __half* __restrict__ Yh,
      float* __restrict__ asrc, float* __restrict__ adst,
      float* __restrict__ asrc2, float* __restrict__ adst2,
      int n, int ntiles) {
    constexpr int NOUT = 128;
    constexpr int NT = 16;                     // n-tiles
    constexpr int WB = NOUT * 272;             // bytes per W split half
    constexpr int AB = 128 * 272;              // bytes per A split half
    extern __shared__ __align__(16) char smem[];
    char* sWh = smem;
    char* sWl = smem + WB;
    char* sA  = smem + 2 * WB;                 // 2 bufs x (Ah | Al)
    float* sAtt = (float*)(smem + 2 * WB + 4 * AB);

    int tid = threadIdx.x, warp = tid >> 5, lane = tid & 31;

    if constexpr (DUAL) {
        for (int i = tid; i < 64; i += 256) {
            sAtt[i] = a_s[i]; sAtt[64 + i] = a_s2[i];
            sAtt[128 + i] = a_d[i]; sAtt[192 + i] = a_d2[i];
        }
    } else {
        for (int i = tid; i < NOUT; i += 256) { sAtt[i] = a_s[i]; sAtt[NOUT + i] = a_d[i]; }
    }

    uint32_t uWh = s2u(sWh), uWl = s2u(sWl), uA = s2u(sA);

    load_tile<NOUT, 256>(uWh, Bh, 0, NOUT, tid);
    load_tile<NOUT, 256>(uWl, Bl, 0, NOUT, tid);
    cp_commit();
    {
        int t0 = blockIdx.x;
        int nr = min(128, n - t0 * 128);
        load_tile<128, 256>(uA, Ah, (size_t)t0 * 128, nr, tid);
        load_tile<128, 256>(uA + AB, Al, (size_t)t0 * 128, nr, tid);
        cp_commit();
    }

    int mi = lane >> 3, l7 = lane & 7;
    uint32_t aoff = (uint32_t)(warp * 16 + ((mi & 1) << 3) + l7) * 272 + ((mi >> 1) << 3) * 2;
    uint32_t boff = (uint32_t)(((mi >> 1) << 3) + l7) * 272 + ((mi & 1) << 3) * 2;

    int buf = 0;
    for (int t = blockIdx.x; t < ntiles; t += gridDim.x) {
        int tn = t + gridDim.x;
        if (tn < ntiles) {
            int nr = min(128, n - tn * 128);
            uint32_t nb = uA + (buf ^ 1) * 2 * AB;
            load_tile<128, 256>(nb, Ah, (size_t)tn * 128, nr, tid);
            load_tile<128, 256>(nb + AB, Al, (size_t)tn * 128, nr, tid);
            cp_commit();
            cp_wait1();
        } else {
            cp_wait0();
        }
        __syncthreads();

        uint32_t uAh = uA + buf * 2 * AB;
        uint32_t uAl = uAh + AB;

        float acc[NT][4];
#pragma unroll
        for (int j = 0; j < NT; j++)
#pragma unroll
            for (int q = 0; q < 4; q++) acc[j][q] = 0.f;

#pragma unroll
        for (int ks = 0; ks < 8; ks++) {
            uint32_t kb = ks * 32;
            uint32_t ah[4], al_[4];
            ldsm4(ah, uAh + aoff + kb);
            ldsm4(al_, uAl + aoff + kb);
#pragma unroll
            for (int j = 0; j < NT; j += 2) {
                uint32_t bh[4], bl_[4];
                uint32_t bo = boff + (uint32_t)j * 8 * 272 + kb;
                ldsm4(bh, uWh + bo);
                ldsm4(bl_, uWl + bo);
                mma16816(acc[j],     ah,  bh);
                mma16816(acc[j + 1], ah,  bh + 2);
                mma16816(acc[j],     ah,  bl_);
                mma16816(acc[j + 1], ah,  bl_ + 2);
                mma16816(acc[j],     al_, bh);
                mma16816(acc[j + 1], al_, bh + 2);
            }
        }

        // epilogue
        int r0 = warp * 16 + (lane >> 2);
        int node0 = t * 128 + r0;
        int node1 = node0 + 8;
        bool v0 = node0 < n, v1 = node1 < n;
        float pa0 = 0.f, pd0 = 0.f, pa1 = 0.f, pd1 = 0.f;   // A-group (mu / full)
        float qa0 = 0.f, qd0 = 0.f, qa1 = 0.f, qd1 = 0.f;   // B-group (logstd, DUAL)
        int cb = (lane & 3) * 2;
#pragma unroll
        for (int j = 0; j < NT; j++) {
            int c = j * 8 + cb;
            float s0 = sAtt[c], s1 = sAtt[c + 1];
            float d0 = sAtt[NOUT + c], d1 = sAtt[NOUT + c + 1];
            if (DUAL && j >= NT / 2) {
                qa0 += acc[j][0] * s0 + acc[j][1] * s1;
                qd0 += acc[j][0] * d0 + acc[j][1] * d1;
                qa1 += acc[j][2] * s0 + acc[j][3] * s1;
                qd1 += acc[j][2] * d0 + acc[j][3] * d1;
            } else {
                pa0 += acc[j][0] * s0 + acc[j][1] * s1;
                pd0 += acc[j][0] * d0 + acc[j][1] * d1;
                pa1 += acc[j][2] * s0 + acc[j][3] * s1;
                pd1 += acc[j][2] * d0 + acc[j][3] * d1;
            }
            if constexpr (DUAL) {
                if (v0) *(float2*)(Yf + (size_t)node0 * NOUT + c) = make_float2(acc[j][0], acc[j][1]);
                if (v1) *(float2*)(Yf + (size_t)node1 * NOUT + c) = make_float2(acc[j][2], acc[j][3]);
            } else {
                if (v0) *(__half2*)(Yh + (size_t)node0 * NOUT + c) = __floats2half2_rn(acc[j][0], acc[j][1]);
                if (v1) *(__half2*)(Yh + (size_t)node1 * NOUT + c) = __floats2half2_rn(acc[j][2], acc[j][3]);
            }
        }
#pragma unroll
        for (int o = 1; o <= 2; o <<= 1) {
            pa0 += __shfl_xor_sync(0xffffffffu, pa0, o);
            pd0 += __shfl_xor_sync(0xffffffffu, pd0, o);
            pa1 += __shfl_xor_sync(0xffffffffu, pa1, o);
            pd1 += __shfl_xor_sync(0xffffffffu, pd1, o);
            if (DUAL) {
                qa0 += __shfl_xor_sync(0xffffffffu, qa0, o);
                qd0 += __shfl_xor_sync(0xffffffffu, qd0, o);
                qa1 += __shfl_xor_sync(0xffffffffu, qa1, o);
                qd1 += __shfl_xor_sync(0xffffffffu, qd1, o);
            }
        }
        if ((lane & 3) == 0) {
            if (v0) {
                asrc[node0] = pa0; adst[node0] = pd0;
                if (DUAL) { asrc2[node0] = qa0; adst2[node0] = qd0; }
            }
            if (v1) {
                asrc[node1] = pa1; adst[node1] = pd1;
                if (DUAL) { asrc2[node1] = qa1; adst2[node1] = qd1; }
            }
        }
        __syncthreads();
        buf ^= 1;
    }
}

// ---------------- fp32 -> bf16 hi/lo split -------------------------------------
__global__ void k_convx(const float* __restrict__ s, __nv_bfloat16* __restrict__ bh,
                        __nv_bfloat16* __restrict__ bl, int n4) {
    int i = blockIdx.x * blockDim.x + threadIdx.x;
    if (i >= n4) return;
    float4 v = ((const float4*)s)[i];
    __nv_bfloat16 h0 = __float2bfloat16(v.x), h1 = __float2bfloat16(v.y);
    __nv_bfloat16 h2 = __float2bfloat16(v.z), h3 = __float2bfloat16(v.w);
    __nv_bfloat16 l0 = __float2bfloat16(v.x - __bfloat162float(h0));
    __nv_bfloat16 l1 = __float2bfloat16(v.y - __bfloat162float(h1));
    __nv_bfloat16 l2 = __float2bfloat16(v.z - __bfloat162float(h2));
    __nv_bfloat16 l3 = __float2bfloat16(v.w - __bfloat162float(h3));
    ((__nv_bfloat162*)bh)[i * 2]     = __nv_bfloat162(h0, h1);
    ((__nv_bfloat162*)bh)[i * 2 + 1] = __nv_bfloat162(h2, h3);
    ((__nv_bfloat162*)bl)[i * 2]     = __nv_bfloat162(l0, l1);
    ((__nv_bfloat162*)bl)[i * 2 + 1] = __nv_bfloat162(l2, l3);
}

// transpose + split all 4 weight matrices into wt[n*128+k] hi/lo
// offsets: W0t=0, W1t=16384, Wmt=32768, Wlt=40960 (combined mu|logstd = 32768..49152)
__global__ void k_convw(const float* __restrict__ W0, const float* __restrict__ W1,
                        const float* __restrict__ Wm, const float* __restrict__ Wl,
                        __nv_bfloat16* __restrict__ wh, __nv_bfloat16* __restrict__ wl_) {
    int i = blockIdx.x * blockDim.x + threadIdx.x;
    if (i >= 49152) return;
    float v;
    if (i < 16384)      { int j = i;         int nn = j >> 7, k = j & 127; v = W0[k * 128 + nn]; }
    else if (i < 32768) { int j = i - 16384; int nn = j >> 7, k = j & 127; v = W1[k * 128 + nn]; }
    else if (i < 40960) { int j = i - 32768; int nn = j >> 7, k = j & 127; v = Wm[k * 64 + nn]; }
    else                { int j = i - 40960; int nn = j >> 7, k = j & 127; v = Wl[k * 64 + nn]; }
    __nv_bfloat16 h = __float2bfloat16(v);
    wh[i] = h;
    wl_[i] = __float2bfloat16(v - __bfloat162float(h));
}

// ---------------- zero scratch -------------------------------------------------
__global__ void k_zero(int* __restrict__ cnt, int* __restrict__ fill,
                       float* __restrict__ sumw, int n) {
    int i = blockIdx.x * blockDim.x + threadIdx.x;
    if (i < n) { cnt[i] = 0; fill[i] = 0; sumw[i] = 0.f; }
}

// ---------------- dtype probe --------------------------------------------------
__global__ void k_probe(const void* __restrict__ ei_raw, int* __restrict__ flag) {
    __shared__ int bad;
    if (threadIdx.x == 0) bad = 0;
    __syncthreads();
    const long long* p = (const long long*)ei_raw;
    for (int i = threadIdx.x; i < 4096; i += blockDim.x) {
        long long v = p[i];
        if (v < 0 || v >= (long long)NN) bad = 1;
    }
    __syncthreads();
    if (threadIdx.x == 0) *flag = bad ? 0 : 1;
}

// histogram of destination degrees (reads edge_index directly)
__global__ void k_hist(const void* __restrict__ ei_raw, const int* __restrict__ flag,
                       int* __restrict__ cnt, int E) {
    int e = blockIdx.x * blockDim.x + threadIdx.x;
    if (e >= E) return;
    int d;
    if (__ldg(flag)) d = (int)((const long long*)ei_raw)[E + e];
    else             d = ((const int*)ei_raw)[E + e];
    atomicAdd(&cnt[d], 1);
}

// ---------------- CSR build ---------------------------------------------------
__global__ void k_scan1(const int* __restrict__ cnt, int* __restrict__ ptr,
                        int* __restrict__ bsum, int n) {
    __shared__ int sm[SCAN_B];
    int i = blockIdx.x * SCAN_B + threadIdx.x;
    int v = (i < n) ? cnt[i] : 0;
    sm[threadIdx.x] = v;
    __syncthreads();
    for (int off = 1; off < SCAN_B; off <<= 1) {
        int t = (threadIdx.x >= off) ? sm[threadIdx.x - off] : 0;
        __syncthreads();
        sm[threadIdx.x] += t;
        __syncthreads();
    }
    if (i < n) ptr[i + 1] = sm[threadIdx.x];
    if (threadIdx.x == SCAN_B - 1) bsum[blockIdx.x] = sm[SCAN_B - 1];
    if (i == 0) ptr[0] = 0;
}

__global__ void k_scan23(int* __restrict__ ptr, const int* __restrict__ bsum, int n) {
    __shared__ int sm[128];
    int t = threadIdx.x;
    if (t < 128) sm[t] = (t < (int)blockIdx.x && t < NB_SCAN) ? bsum[t] : 0;
    __syncthreads();
    for (int off = 64; off; off >>= 1) {
        if (t < off) sm[t] += sm[t + off];
        __syncthreads();
    }
    int offs = sm[0];
    int i = blockIdx.x * SCAN_B + t;
    if (i < n) ptr[i + 1] += offs;
}

__global__ void k_scatter(const void* __restrict__ ei_raw, const int* __restrict__ flag,
                          const float* __restrict__ ew,
                          const int* __restrict__ ptr, int* __restrict__ fill,
                          int* __restrict__ csrc, float* __restrict__ csw,
                          float* __restrict__ sumw, int E) {
    int e = blockIdx.x * blockDim.x + threadIdx.x;
    if (e >= E) return;
    int s, d;
    if (__ldg(flag)) {
        const long long* p = (const long long*)ei_raw;
        s = (int)p[e]; d = (int)p[E + e];
    } else {
        const int* p = (const int*)ei_raw;
        s = p[e]; d = p[E + e];
    }
    float w = ew[e];
    int pos = ptr[d] + atomicAdd(&fill[d], 1);
    csrc[pos] = s;
    csw[pos] = w;
    atomicAdd(&sumw[d], w);
}

// fused: 3 edge-attention dots (block 0) + self-loop attr (blocks 1..)
__global__ void k_misc(const int* __restrict__ cnt, const float* __restrict__ sumw,
                       float* __restrict__ la,
                       const float* __restrict__ We0, const float* __restrict__ ae0,
                       const float* __restrict__ We1, const float* __restrict__ ae1,
                       const float* __restrict__ Wem, const float* __restrict__ aem,
                       float* __restrict__ c, int n) {
    if (blockIdx.x == 0) {
        int w = threadIdx.x >> 5, lane = threadIdx.x & 31;
        if (w < 3) {
            const float* A = (w == 0) ? We0 : ((w == 1) ? We1 : Wem);
            const float* B = (w == 0) ? ae0 : ((w == 1) ? ae1 : aem);
            int len = (w == 2) ? 64 : 128;
            float p = 0.f;
            for (int i = lane; i < len; i += 32) p += A[i] * B[i];
#pragma unroll
            for (int off = 16; off; off >>= 1) p += __shfl_xor_sync(0xffffffffu, p, off);
            if (lane == 0) c[w] = p;
        }
    } else {
        int i = (blockIdx.x - 1) * blockDim.x + threadIdx.x;
        if (i < n) {
            int cc = cnt[i];
            la[i] = (cc > 0) ? (sumw[i] / (float)cc) : 0.0f;
        }
    }
}

// ---------------- aggregation (layers 0/1): softmax gather over fp16 xl --------
__device__ __forceinline__ float lrelu(float a) { return a > 0.f ? a : 0.2f * a; }

__global__ void k_aggregate(const __half* __restrict__ xl, const float* __restrict__ asrc,
                            const float* __restrict__ adst, const int* __restrict__ ptr,
                            const int* __restrict__ csrc, const float* __restrict__ csw,
                            const float* __restrict__ la, const float* __restrict__ cvec,
                            int cidx, const float* __restrict__ bias,
                            __nv_bfloat16* __restrict__ obh, __nv_bfloat16* __restrict__ obl,
                            int n) {
    int wid = (blockIdx.x * blockDim.x + threadIdx.x) >> 5;
    int lane = threadIdx.x & 31;
    if (wid >= n) return;
    int v = wid;

    float c = cvec[cidx];
    float adv = adst[v];

    float a0 = lrelu(asrc[v] + adv + la[v] * c);
    int rs = ptr[v], re = ptr[v + 1];

    // pass A: exact max
    float m = a0;
    for (int e = rs + lane; e < re; e += 32)
        m = fmaxf(m, lrelu(asrc[csrc[e]] + adv + csw[e] * c));
#pragma unroll
    for (int o = 16; o; o >>= 1) m = fmaxf(m, __shfl_xor_sync(0xffffffffu, m, o));

    // pass B: fixed weights; each lane handles 4 columns (8B fp16 load per row)
    float w0 = __expf(a0 - m);
    float denp = (lane == 0) ? w0 : 0.f;
    float acc[4];
    {
        float2 raw = ((const float2*)(xl + (size_t)v * 128))[lane];
        float2 f01 = __half22float2(*(__half2*)&raw.x);
        float2 f23 = __half22float2(*(__half2*)&raw.y);
        acc[0] = w0 * f01.x; acc[1] = w0 * f01.y;
        acc[2] = w0 * f23.x; acc[3] = w0 * f23.y;
    }
    for (int b = rs; b < re; b += 32) {
        int e = b + lane;
        float w = 0.f;
        int sIdx = 0;
        if (e < re) {
            sIdx = csrc[e];
            w = __expf(lrelu(asrc[sIdx] + adv + csw[e] * c) - m);
        }
        denp += w;
        int cnt = min(32, re - b);
#pragma unroll 4
        for (int j = 0; j < cnt; j++) {
            float wj = __shfl_sync(0xffffffffu, w, j);
            int sj = __shfl_sync(0xffffffffu, sIdx, j);
            float2 raw = ((const float2*)(xl + (size_t)sj * 128))[lane];
            float2 f01 = __half22float2(*(__half2*)&raw.x);
            float2 f23 = __half22float2(*(__half2*)&raw.y);
            acc[0] += wj * f01.x; acc[1] += wj * f01.y;
            acc[2] += wj * f23.x; acc[3] += wj * f23.y;
        }
    }
#pragma unroll
    for (int o = 16; o; o >>= 1) denp += __shfl_xor_sync(0xffffffffu, denp, o);
    float inv = 1.0f / denp;

    float4 bv = ((const float4*)bias)[lane];
    float o_[4];
    o_[0] = fmaxf(acc[0] * inv + bv.x, 0.f);
    o_[1] = fmaxf(acc[1] * inv + bv.y, 0.f);
    o_[2] = fmaxf(acc[2] * inv + bv.z, 0.f);
    o_[3] = fmaxf(acc[3] * inv + bv.w, 0.f);

    __nv_bfloat16 h[4], l[4];
#pragma unroll
    for (int i = 0; i < 4; i++) {
        h[i] = __float2bfloat16(o_[i]);
        l[i] = __float2bfloat16(o_[i] - __bfloat162float(h[i]));
    }
    __nv_bfloat162* ph = (__nv_bfloat162*)(obh + (size_t)v * 128) + lane * 2;
    __nv_bfloat162* pl = (__nv_bfloat162*)(obl + (size_t)v * 128) + lane * 2;
    ph[0] = __nv_bfloat162(h[0], h[1]); ph[1] = __nv_bfloat162(h[2], h[3]);
    pl[0] = __nv_bfloat162(l[0], l[1]); pl[1] = __nv_bfloat162(l[2], l[3]);
}

// ---------------- fused mu+logstd aggregation (fp32 gather) --------------------
// xl rows are [mu cols 0-63 | logstd cols 64-127]. Lanes 0-15 apply mu weights,
// lanes 16-31 logstd weights; one gather serves both heads.
__global__ void k_aggdual(const float* __restrict__ xl,
                          const float* __restrict__ asrcA, const float* __restrict__ adstA,
                          const float* __restrict__ asrcB, const float* __restrict__ adstB,
                          const int* __restrict__ ptr, const int* __restrict__ csrc,
                          const float* __restrict__ csw, const float* __restrict__ la,
                          const float* __restrict__ cvec,
                          const float* __restrict__ biasA, const float* __restrict__ biasB,
                          float* __restrict__ outA, float* __restrict__ outB, int n) {
    int wid = (blockIdx.x * blockDim.x + threadIdx.x) >> 5;
    int lane = threadIdx.x & 31;
    if (wid >= n) return;
    int v = wid;
    bool isA = lane < 16;

    float c = cvec[2];
    float advA = adstA[v], advB = adstB[v];
    float lav = la[v];

    float a0A = lrelu(asrcA[v] + advA + lav * c);
    float a0B = lrelu(asrcB[v] + advB);
    int rs = ptr[v], re = ptr[v + 1];

    float mA = a0A, mB = a0B;
    for (int e = rs + lane; e < re; e += 32) {
        int s = csrc[e];
        mA = fmaxf(mA, lrelu(asrcA[s] + advA + csw[e] * c));
        mB = fmaxf(mB, lrelu(asrcB[s] + advB));
    }
#pragma unroll
    for (int o = 16; o; o >>= 1) {
        mA = fmaxf(mA, __shfl_xor_sync(0xffffffffu, mA, o));
        mB = fmaxf(mB, __shfl_xor_sync(0xffffffffu, mB, o));
    }

    float w0A = __expf(a0A - mA), w0B = __expf(a0B - mB);
    float denA = (lane == 0) ? w0A : 0.f;
    float denB = (lane == 0) ? w0B : 0.f;
    float wsel0 = isA ? w0A : w0B;
    float acc[4];
    {
        float4 t = ((const float4*)(xl + (size_t)v * 128))[lane];
        acc[0] = wsel0 * t.x; acc[1] = wsel0 * t.y;
        acc[2] = wsel0 * t.z; acc[3] = wsel0 * t.w;
    }
    for (int b = rs; b < re; b += 32) {
        int e = b + lane;
        float wA = 0.f, wB = 0.f;
        int sIdx = 0;
        if (e < re) {
            sIdx = csrc[e];
            wA = __expf(lrelu(asrcA[sIdx] + advA + csw[e] * c) - mA);
            wB = __expf(lrelu(asrcB[sIdx] + advB) - mB);
        }
        denA += wA; denB += wB;
        int cnt = min(32, re - b);
#pragma unroll 4
        for (int j = 0; j < cnt; j++) {
            float wjA = __shfl_sync(0xffffffffu, wA, j);
            float wjB = __shfl_sync(0xffffffffu, wB, j);
            int sj = __shfl_sync(0xffffffffu, sIdx, j);
            float wj = isA ? wjA : wjB;
            float4 t = ((const float4*)(xl + (size_t)sj * 128))[lane];
            acc[0] += wj * t.x; acc[1] += wj * t.y;
            acc[2] += wj * t.z; acc[3] += wj * t.w;
        }
    }
#pragma unroll
    for (int o = 16; o; o >>= 1) {
        denA += __shfl_xor_sync(0xffffffffu, denA, o);
        denB += __shfl_xor_sync(0xffffffffu, denB, o);
    }
    float inv = isA ? (1.0f / denA) : (1.0f / denB);

    if (isA) {
        float4 bv = ((const float4*)biasA)[lane];
        ((float4*)(outA + (size_t)v * 64))[lane] =
            make_float4(acc[0] * inv + bv.x, acc[1] * inv + bv.y,
                        acc[2] * inv + bv.z, acc[3] * inv + bv.w);
    } else {
        float4 bv = ((const float4*)biasB)[lane - 16];
        ((float4*)(outB + (size_t)v * 64))[lane - 16] =
            make_float4(acc[0] * inv + bv.x, acc[1] * inv + bv.y,
                        acc[2] * inv + bv.z, acc[3] * inv + bv.w);
    }
}

// ---------------- launch ------------------------------------------------------
extern "C" void kernel_launch(void* const* d_in, const int* in_sizes, int n_in,
                              void* d_out, int out_size) {
    const float* x      = (const float*)d_in[0];
    const void*  ei_raw = d_in[1];          // int32 or int64, probed at runtime
    const float* ew     = (const float*)d_in[2];
    const float *W0 = (const float*)d_in[3],  *as0 = (const float*)d_in[4],
                *ad0 = (const float*)d_in[5], *ae0 = (const float*)d_in[6],
                *We0 = (const float*)d_in[7], *b0  = (const float*)d_in[8];
    const float *W1 = (const float*)d_in[9],  *as1 = (const float*)d_in[10],
                *ad1 = (const float*)d_in[11], *ae1 = (const float*)d_in[12],
                *We1 = (const float*)d_in[13], *b1  = (const float*)d_in[14];
    const float *Wm = (const float*)d_in[15], *asm_ = (const float*)d_in[16],
                *adm = (const float*)d_in[17], *aem = (const float*)d_in[18],
                *Wem = (const float*)d_in[19], *bm  = (const float*)d_in[20];
    const float *Wl = (const float*)d_in[21], *asl = (const float*)d_in[22],
                *adl = (const float*)d_in[23], *bl  = (const float*)d_in[24];
    float* out = (float*)d_out;

    int *p_flag, *p_cnt, *p_fill, *p_ptr, *p_bsum, *p_csrc;
    float *p_csw, *p_sumw, *p_loop, *p_xl, *p_asrc, *p_adst, *p_asrc2, *p_adst2, *p_c;
    __nv_bfloat16 *p_bh, *p_bl, *p_wh, *p_wl;
    cudaGetSymbolAddress((void**)&p_flag, g_flag64);
    cudaGetSymbolAddress((void**)&p_cnt,  g_cnt);
    cudaGetSymbolAddress((void**)&p_fill, g_fill);
    cudaGetSymbolAddress((void**)&p_ptr,  g_ptr);
    cudaGetSymbolAddress((void**)&p_bsum, g_bsum);
    cudaGetSymbolAddress((void**)&p_csrc, g_csrc);
    cudaGetSymbolAddress((void**)&p_csw,  g_csw);
    cudaGetSymbolAddress((void**)&p_sumw, g_sumw);
    cudaGetSymbolAddress((void**)&p_loop, g_loop);
    cudaGetSymbolAddress((void**)&p_xl,   g_xl);
    cudaGetSymbolAddress((void**)&p_asrc, g_asrc);
    cudaGetSymbolAddress((void**)&p_adst, g_adst);
    cudaGetSymbolAddress((void**)&p_asrc2, g_asrc2);
    cudaGetSymbolAddress((void**)&p_adst2, g_adst2);
    cudaGetSymbolAddress((void**)&p_c,    g_c);
    cudaGetSymbolAddress((void**)&p_bh,   g_bh);
    cudaGetSymbolAddress((void**)&p_bl,   g_bl);
    cudaGetSymbolAddress((void**)&p_wh,   g_wh);
    cudaGetSymbolAddress((void**)&p_wl,   g_wl);
    __half* p_xlh = (__half*)p_xl;       // fp16 alias for layers 0/1

    const int sm128 = 2 * (128 * 272) + 4 * (128 * 272) + 2 * 128 * 4;
    cudaFuncSetAttribute(k_mma<false>, cudaFuncAttributeMaxDynamicSharedMemorySize, sm128);
    cudaFuncSetAttribute(k_mma<true>,  cudaFuncAttributeMaxDynamicSharedMemorySize, sm128);

    const int agg_blocks = (NN + 7) / 8;     // 8 warps/block, warp per node
    const int cx_blocks  = (NN * 128 / 4 + 255) / 256;

    // 1: weight transpose + bf16 split
    k_convw<<<(49152 + 255) / 256, 256>>>(W0, W1, Wm, Wl, p_wh, p_wl);
    // 2: split input x
    k_convx<<<cx_blocks, 256>>>(x, p_bh, p_bl, NN * 128 / 4);
    // 3: zero scratch
    k_zero<<<(NN + 255) / 256, 256>>>(p_cnt, p_fill, p_sumw, NN);
    // 4: layer-0 GEMM (profiled slot) -> fp16 xl
    k_mma<false><<<MMA_GRID, 256, sm128>>>(p_bh, p_bl, p_wh, p_wl, as0, ad0,
                                           nullptr, nullptr, nullptr, p_xlh,
                                           p_asrc, p_adst, nullptr, nullptr, NN, NTILES);
    // 5-9: CSR build
    k_probe<<<1, 256>>>(ei_raw, p_flag);
    k_hist<<<(NE + 255) / 256, 256>>>(ei_raw, p_flag, p_cnt, NE);
    k_scan1<<<NB_SCAN, SCAN_B>>>(p_cnt, p_ptr, p_bsum, NN);
    k_scan23<<<NB_SCAN, SCAN_B>>>(p_ptr, p_bsum, NN);
    k_scatter<<<(NE + 255) / 256, 256>>>(ei_raw, p_flag, ew, p_ptr, p_fill,
                                         p_csrc, p_csw, p_sumw, NE);
    // 10: edge-attention scalars + self-loop attrs
    k_misc<<<1 + (NN + 255) / 256, 256>>>(p_cnt, p_sumw, p_loop,
                                          We0, ae0, We1, ae1, Wem, aem, p_c, NN);

    // layer 0 aggregate (fp16 gather) -> bf16 split
    k_aggregate<<<agg_blocks, 256>>>(p_xlh, p_asrc, p_adst, p_ptr, p_csrc, p_csw,
                                     p_loop, p_c, 0, b0, p_bh, p_bl, NN);
    // layer 1
    k_mma<false><<<MMA_GRID, 256, sm128>>>(p_bh, p_bl, p_wh + 16384, p_wl + 16384, as1, ad1,
                                           nullptr, nullptr, nullptr, p_xlh,
                                           p_asrc, p_adst, nullptr, nullptr, NN, NTILES);
    k_aggregate<<<agg_blocks, 256>>>(p_xlh, p_asrc, p_adst, p_ptr, p_csrc, p_csw,
                                     p_loop, p_c, 1, b1, p_bh, p_bl, NN);
    // mu+logstd fused GEMM (combined weights at offset 32768) -> fp32 xl
    k_mma<true><<<MMA_GRID, 256, sm128>>>(p_bh, p_bl, p_wh + 32768, p_wl + 32768,
                                          asm_, adm, asl, adl, p_xl, nullptr,
                                          p_asrc, p_adst, p_asrc2, p_adst2, NN, NTILES);
    // fused mu+logstd aggregation (fp32 gather for final outputs)
    k_aggdual<<<agg_blocks, 256>>>(p_xl, p_asrc, p_adst, p_asrc2, p_adst2,
                                   p_ptr, p_csrc, p_csw, p_loop, p_c,
                                   bm, bl, out, out + (size_t)NN * 64, NN);
}

// round 10
// speedup vs baseline: 1.8445x; 1.0042x over previous
#include <cuda_runtime.h>
#include <cuda_bf16.h>
#include <cuda_fp16.h>
#include <cstdint>

// Problem constants (fixed by the dataset)
#define NN 100000
#define NE 1600000
#define SCAN_B 1024
#define NB_SCAN ((NN + SCAN_B - 1) / SCAN_B)   // 98
#define NTILES ((NN + 127) / 128)              // 782
#define MMA_GRID 148

// ---------------- scratch (device globals; no allocation allowed) -------------
__device__ int   g_flag64;           // 1 if edge_index buffer is int64
__device__ int   g_cnt[NN];
__device__ int   g_fill[NN];
__device__ int   g_ptr[NN + 1];
__device__ int   g_bsum[128];
__device__ int   g_csrc[NE];
__device__ float g_csw[NE];
__device__ float g_sumw[NN];
__device__ float g_loop[NN];
__device__ float g_xl[(size_t)NN * 128];   // aliased as half (all layers gather fp16)
__device__ float g_asrc[NN];
__device__ float g_adst[NN];
__device__ float g_asrc2[NN];
__device__ float g_adst2[NN];
__device__ float g_c[4];
__device__ __nv_bfloat16 g_bh[(size_t)NN * 128];
__device__ __nv_bfloat16 g_bl[(size_t)NN * 128];
__device__ __nv_bfloat16 g_wh[49152];
__device__ __nv_bfloat16 g_wl[49152];

// ---------------- helpers -------------------------------------------------------
__device__ __forceinline__ uint32_t s2u(const void* p) {
    uint32_t a;
    asm("{ .reg .u64 t; cvta.to.shared.u64 t, %1; cvt.u32.u64 %0, t; }"
        : "=r"(a) : "l"(p));
    return a;
}
__device__ __forceinline__ void cp16(uint32_t saddr, const void* g, int sz) {
    asm volatile("cp.async.cg.shared.global [%0], [%1], 16, %2;"
                 :: "r"(saddr), "l"(g), "r"(sz));
}
__device__ __forceinline__ void cp_commit() {
    asm volatile("cp.async.commit_group;" ::: "memory");
}
__device__ __forceinline__ void cp_wait1() {
    asm volatile("cp.async.wait_group 1;" ::: "memory");
}
__device__ __forceinline__ void cp_wait0() {
    asm volatile("cp.async.wait_group 0;" ::: "memory");
}
__device__ __forceinline__ void ldsm4(uint32_t* r, uint32_t addr) {
    asm volatile("ldmatrix.sync.aligned.m8n8.x4.shared.b16 {%0,%1,%2,%3}, [%4];"
                 : "=r"(r[0]), "=r"(r[1]), "=r"(r[2]), "=r"(r[3]) : "r"(addr));
}
__device__ __forceinline__ void mma16816(float* d, const uint32_t* a, const uint32_t* b) {
    asm volatile(
        "mma.sync.aligned.m16n8k16.row.col.f32.bf16.bf16.f32 "
        "{%0,%1,%2,%3}, {%4,%5,%6,%7}, {%8,%9}, {%0,%1,%2,%3};"
        : "+f"(d[0]), "+f"(d[1]), "+f"(d[2]), "+f"(d[3])
        : "r"(a[0]), "r"(a[1]), "r"(a[2]), "r"(a[3]), "r"(b[0]), "r"(b[1]));
}

// async-load a [ROWS x 128] bf16 K-major tile into smem, padded stride 272B
template <int ROWS, int NTHR>
__device__ __forceinline__ void load_tile(uint32_t sbase, const __nv_bfloat16* src,
                                          size_t row0, int nrows, int tid) {
#pragma unroll 4
    for (int c = tid; c < ROWS * 16; c += NTHR) {
        int row = c >> 4, kc = c & 15;
        uint32_t off = (uint32_t)row * 272 + kc * 16;
        size_t grow = (row < nrows) ? (row0 + row) : row0;
        cp16(sbase + off, src + grow * 128 + kc * 8, (row < nrows) ? 16 : 0);
    }
}

// ---------------- GEMM via mma.sync bf16x3 split --------------------------------
// Y[n,128] = X[n,128] @ W[128,128]; 3 passes AhBh + AhBl + AlBh, fp32 accumulate.
// Y always written fp16 (feeds the bandwidth-bound aggregation gathers).
// DUAL: W = [Wm_t ; Wl_t]; epilogue emits mu attention dots (cols 0-63) into
// asrc/adst and logstd dots (cols 64-127) into asrc2/adst2.
template <bool DUAL>
__global__ void __launch_bounds__(256, 1)
k_mma(const __nv_bfloat16* __restrict__ Ah, const __nv_bfloat16* __restrict__ Al,
      const __nv_bfloat16* __restrict__ Bh, const __nv_bfloat16* __restrict__ Bl,
      const float* __restrict__ a_s, const float* __restrict__ a_d,
      const float* __restrict__ a_s2, const float* __restrict__ a_d2,
      __half* __restrict__ Yh,
      float* __restrict__ asrc, float* __restrict__ adst,
      float* __restrict__ asrc2, float* __restrict__ adst2,
      int n, int ntiles) {
    constexpr int NOUT = 128;
    constexpr int NT = 16;                     // n-tiles
    constexpr int WB = NOUT * 272;             // bytes per W split half
    constexpr int AB = 128 * 272;              // bytes per A split half
    extern __shared__ __align__(16) char smem[];
    char* sWh = smem;
    char* sWl = smem + WB;
    char* sA  = smem + 2 * WB;                 // 2 bufs x (Ah | Al)
    float* sAtt = (float*)(smem + 2 * WB + 4 * AB);

    int tid = threadIdx.x, warp = tid >> 5, lane = tid & 31;

    if constexpr (DUAL) {
        for (int i = tid; i < 64; i += 256) {
            sAtt[i] = a_s[i]; sAtt[64 + i] = a_s2[i];
            sAtt[128 + i] = a_d[i]; sAtt[192 + i] = a_d2[i];
        }
    } else {
        for (int i = tid; i < NOUT; i += 256) { sAtt[i] = a_s[i]; sAtt[NOUT + i] = a_d[i]; }
    }

    uint32_t uWh = s2u(sWh), uWl = s2u(sWl), uA = s2u(sA);

    load_tile<NOUT, 256>(uWh, Bh, 0, NOUT, tid);
    load_tile<NOUT, 256>(uWl, Bl, 0, NOUT, tid);
    cp_commit();
    {
        int t0 = blockIdx.x;
        int nr = min(128, n - t0 * 128);
        load_tile<128, 256>(uA, Ah, (size_t)t0 * 128, nr, tid);
        load_tile<128, 256>(uA + AB, Al, (size_t)t0 * 128, nr, tid);
        cp_commit();
    }

    int mi = lane >> 3, l7 = lane & 7;
    uint32_t aoff = (uint32_t)(warp * 16 + ((mi & 1) << 3) + l7) * 272 + ((mi >> 1) << 3) * 2;
    uint32_t boff = (uint32_t)(((mi >> 1) << 3) + l7) * 272 + ((mi & 1) << 3) * 2;

    int buf = 0;
    for (int t = blockIdx.x; t < ntiles; t += gridDim.x) {
        int tn = t + gridDim.x;
        if (tn < ntiles) {
            int nr = min(128, n - tn * 128);
            uint32_t nb = uA + (buf ^ 1) * 2 * AB;
            load_tile<128, 256>(nb, Ah, (size_t)tn * 128, nr, tid);
            load_tile<128, 256>(nb + AB, Al, (size_t)tn * 128, nr, tid);
            cp_commit();
            cp_wait1();
        } else {
            cp_wait0();
        }
        __syncthreads();

        uint32_t uAh = uA + buf * 2 * AB;
        uint32_t uAl = uAh + AB;

        float acc[NT][4];
#pragma unroll
        for (int j = 0; j < NT; j++)
#pragma unroll
            for (int q = 0; q < 4; q++) acc[j][q] = 0.f;

#pragma unroll
        for (int ks = 0; ks < 8; ks++) {
            uint32_t kb = ks * 32;
            uint32_t ah[4], al_[4];
            ldsm4(ah, uAh + aoff + kb);
            ldsm4(al_, uAl + aoff + kb);
#pragma unroll
            for (int j = 0; j < NT; j += 2) {
                uint32_t bh[4], bl_[4];
                uint32_t bo = boff + (uint32_t)j * 8 * 272 + kb;
                ldsm4(bh, uWh + bo);
                ldsm4(bl_, uWl + bo);
                mma16816(acc[j],     ah,  bh);
                mma16816(acc[j + 1], ah,  bh + 2);
                mma16816(acc[j],     ah,  bl_);
                mma16816(acc[j + 1], ah,  bl_ + 2);
                mma16816(acc[j],     al_, bh);
                mma16816(acc[j + 1], al_, bh + 2);
            }
        }

        // epilogue
        int r0 = warp * 16 + (lane >> 2);
        int node0 = t * 128 + r0;
        int node1 = node0 + 8;
        bool v0 = node0 < n, v1 = node1 < n;
        float pa0 = 0.f, pd0 = 0.f, pa1 = 0.f, pd1 = 0.f;   // A-group (mu / full)
        float qa0 = 0.f, qd0 = 0.f, qa1 = 0.f, qd1 = 0.f;   // B-group (logstd, DUAL)
        int cb = (lane & 3) * 2;
#pragma unroll
        for (int j = 0; j < NT; j++) {
            int c = j * 8 + cb;
            float s0 = sAtt[c], s1 = sAtt[c + 1];
            float d0 = sAtt[NOUT + c], d1 = sAtt[NOUT + c + 1];
            if (DUAL && j >= NT / 2) {
                qa0 += acc[j][0] * s0 + acc[j][1] * s1;
                qd0 += acc[j][0] * d0 + acc[j][1] * d1;
                qa1 += acc[j][2] * s0 + acc[j][3] * s1;
                qd1 += acc[j][2] * d0 + acc[j][3] * d1;
            } else {
                pa0 += acc[j][0] * s0 + acc[j][1] * s1;
                pd0 += acc[j][0] * d0 + acc[j][1] * d1;
                pa1 += acc[j][2] * s0 + acc[j][3] * s1;
                pd1 += acc[j][2] * d0 + acc[j][3] * d1;
            }
            if (v0) *(__half2*)(Yh + (size_t)node0 * NOUT + c) = __floats2half2_rn(acc[j][0], acc[j][1]);
            if (v1) *(__half2*)(Yh + (size_t)node1 * NOUT + c) = __floats2half2_rn(acc[j][2], acc[j][3]);
        }
#pragma unroll
        for (int o = 1; o <= 2; o <<= 1) {
            pa0 += __shfl_xor_sync(0xffffffffu, pa0, o);
            pd0 += __shfl_xor_sync(0xffffffffu, pd0, o);
            pa1 += __shfl_xor_sync(0xffffffffu, pa1, o);
            pd1 += __shfl_xor_sync(0xffffffffu, pd1, o);
            if (DUAL) {
                qa0 += __shfl_xor_sync(0xffffffffu, qa0, o);
                qd0 += __shfl_xor_sync(0xffffffffu, qd0, o);
                qa1 += __shfl_xor_sync(0xffffffffu, qa1, o);
                qd1 += __shfl_xor_sync(0xffffffffu, qd1, o);
            }
        }
        if ((lane & 3) == 0) {
            if (v0) {
                asrc[node0] = pa0; adst[node0] = pd0;
                if (DUAL) { asrc2[node0] = qa0; adst2[node0] = qd0; }
            }
            if (v1) {
                asrc[node1] = pa1; adst[node1] = pd1;
                if (DUAL) { asrc2[node1] = qa1; adst2[node1] = qd1; }
            }
        }
        __syncthreads();
        buf ^= 1;
    }
}

// ---------------- fp32 -> bf16 hi/lo split -------------------------------------
__global__ void k_convx(const float* __restrict__ s, __nv_bfloat16* __restrict__ bh,
                        __nv_bfloat16* __restrict__ bl, int n4) {
    int i = blockIdx.x * blockDim.x + threadIdx.x;
    if (i >= n4) return;
    float4 v = ((const float4*)s)[i];
    __nv_bfloat16 h0 = __float2bfloat16(v.x), h1 = __float2bfloat16(v.y);
    __nv_bfloat16 h2 = __float2bfloat16(v.z), h3 = __float2bfloat16(v.w);
    __nv_bfloat16 l0 = __float2bfloat16(v.x - __bfloat162float(h0));
    __nv_bfloat16 l1 = __float2bfloat16(v.y - __bfloat162float(h1));
    __nv_bfloat16 l2 = __float2bfloat16(v.z - __bfloat162float(h2));
    __nv_bfloat16 l3 = __float2bfloat16(v.w - __bfloat162float(h3));
    ((__nv_bfloat162*)bh)[i * 2]     = __nv_bfloat162(h0, h1);
    ((__nv_bfloat162*)bh)[i * 2 + 1] = __nv_bfloat162(h2, h3);
    ((__nv_bfloat162*)bl)[i * 2]     = __nv_bfloat162(l0, l1);
    ((__nv_bfloat162*)bl)[i * 2 + 1] = __nv_bfloat162(l2, l3);
}

// transpose + split all 4 weight matrices into wt[n*128+k] hi/lo
// offsets: W0t=0, W1t=16384, Wmt=32768, Wlt=40960 (combined mu|logstd = 32768..49152)
__global__ void k_convw(const float* __restrict__ W0, const float* __restrict__ W1,
                        const float* __restrict__ Wm, const float* __restrict__ Wl,
                        __nv_bfloat16* __restrict__ wh, __nv_bfloat16* __restrict__ wl_) {
    int i = blockIdx.x * blockDim.x + threadIdx.x;
    if (i >= 49152) return;
    float v;
    if (i < 16384)      { int j = i;         int nn = j >> 7, k = j & 127; v = W0[k * 128 + nn]; }
    else if (i < 32768) { int j = i - 16384; int nn = j >> 7, k = j & 127; v = W1[k * 128 + nn]; }
    else if (i < 40960) { int j = i - 32768; int nn = j >> 7, k = j & 127; v = Wm[k * 64 + nn]; }
    else                { int j = i - 40960; int nn = j >> 7, k = j & 127; v = Wl[k * 64 + nn]; }
    __nv_bfloat16 h = __float2bfloat16(v);
    wh[i] = h;
    wl_[i] = __float2bfloat16(v - __bfloat162float(h));
}

// ---------------- zero scratch -------------------------------------------------
__global__ void k_zero(int* __restrict__ cnt, int* __restrict__ fill,
                       float* __restrict__ sumw, int n) {
    int i = blockIdx.x * blockDim.x + threadIdx.x;
    if (i < n) { cnt[i] = 0; fill[i] = 0; sumw[i] = 0.f; }
}

// ---------------- dtype probe --------------------------------------------------
__global__ void k_probe(const void* __restrict__ ei_raw, int* __restrict__ flag) {
    __shared__ int bad;
    if (threadIdx.x == 0) bad = 0;
    __syncthreads();
    const long long* p = (const long long*)ei_raw;
    for (int i = threadIdx.x; i < 4096; i += blockDim.x) {
        long long v = p[i];
        if (v < 0 || v >= (long long)NN) bad = 1;
    }
    __syncthreads();
    if (threadIdx.x == 0) *flag = bad ? 0 : 1;
}

// histogram of destination degrees (reads edge_index directly)
__global__ void k_hist(const void* __restrict__ ei_raw, const int* __restrict__ flag,
                       int* __restrict__ cnt, int E) {
    int e = blockIdx.x * blockDim.x + threadIdx.x;
    if (e >= E) return;
    int d;
    if (__ldg(flag)) d = (int)((const long long*)ei_raw)[E + e];
    else             d = ((const int*)ei_raw)[E + e];
    atomicAdd(&cnt[d], 1);
}

// ---------------- CSR build ---------------------------------------------------
__global__ void k_scan1(const int* __restrict__ cnt, int* __restrict__ ptr,
                        int* __restrict__ bsum, int n) {
    __shared__ int sm[SCAN_B];
    int i = blockIdx.x * SCAN_B + threadIdx.x;
    int v = (i < n) ? cnt[i] : 0;
    sm[threadIdx.x] = v;
    __syncthreads();
    for (int off = 1; off < SCAN_B; off <<= 1) {
        int t = (threadIdx.x >= off) ? sm[threadIdx.x - off] : 0;
        __syncthreads();
        sm[threadIdx.x] += t;
        __syncthreads();
    }
    if (i < n) ptr[i + 1] = sm[threadIdx.x];
    if (threadIdx.x == SCAN_B - 1) bsum[blockIdx.x] = sm[SCAN_B - 1];
    if (i == 0) ptr[0] = 0;
}

__global__ void k_scan23(int* __restrict__ ptr, const int* __restrict__ bsum, int n) {
    __shared__ int sm[128];
    int t = threadIdx.x;
    if (t < 128) sm[t] = (t < (int)blockIdx.x && t < NB_SCAN) ? bsum[t] : 0;
    __syncthreads();
    for (int off = 64; off; off >>= 1) {
        if (t < off) sm[t] += sm[t + off];
        __syncthreads();
    }
    int offs = sm[0];
    int i = blockIdx.x * SCAN_B + t;
    if (i < n) ptr[i + 1] += offs;
}

__global__ void k_scatter(const void* __restrict__ ei_raw, const int* __restrict__ flag,
                          const float* __restrict__ ew,
                          const int* __restrict__ ptr, int* __restrict__ fill,
                          int* __restrict__ csrc, float* __restrict__ csw,
                          float* __restrict__ sumw, int E) {
    int e = blockIdx.x * blockDim.x + threadIdx.x;
    if (e >= E) return;
    int s, d;
    if (__ldg(flag)) {
        const long long* p = (const long long*)ei_raw;
        s = (int)p[e]; d = (int)p[E + e];
    } else {
        const int* p = (const int*)ei_raw;
        s = p[e]; d = p[E + e];
    }
    float w = ew[e];
    int pos = ptr[d] + atomicAdd(&fill[d], 1);
    csrc[pos] = s;
    csw[pos] = w;
    atomicAdd(&sumw[d], w);
}

// fused: 3 edge-attention dots (block 0) + self-loop attr (blocks 1..)
__global__ void k_misc(const int* __restrict__ cnt, const float* __restrict__ sumw,
                       float* __restrict__ la,
                       const float* __restrict__ We0, const float* __restrict__ ae0,
                       const float* __restrict__ We1, const float* __restrict__ ae1,
                       const float* __restrict__ Wem, const float* __restrict__ aem,
                       float* __restrict__ c, int n) {
    if (blockIdx.x == 0) {
        int w = threadIdx.x >> 5, lane = threadIdx.x & 31;
        if (w < 3) {
            const float* A = (w == 0) ? We0 : ((w == 1) ? We1 : Wem);
            const float* B = (w == 0) ? ae0 : ((w == 1) ? ae1 : aem);
            int len = (w == 2) ? 64 : 128;
            float p = 0.f;
            for (int i = lane; i < len; i += 32) p += A[i] * B[i];
#pragma unroll
            for (int off = 16; off; off >>= 1) p += __shfl_xor_sync(0xffffffffu, p, off);
            if (lane == 0) c[w] = p;
        }
    } else {
        int i = (blockIdx.x - 1) * blockDim.x + threadIdx.x;
        if (i < n) {
            int cc = cnt[i];
            la[i] = (cc > 0) ? (sumw[i] / (float)cc) : 0.0f;
        }
    }
}

// ---------------- aggregation (layers 0/1): softmax gather over fp16 xl --------
__device__ __forceinline__ float lrelu(float a) { return a > 0.f ? a : 0.2f * a; }

__global__ void k_aggregate(const __half* __restrict__ xl, const float* __restrict__ asrc,
                            const float* __restrict__ adst, const int* __restrict__ ptr,
                            const int* __restrict__ csrc, const float* __restrict__ csw,
                            const float* __restrict__ la, const float* __restrict__ cvec,
                            int cidx, const float* __restrict__ bias,
                            __nv_bfloat16* __restrict__ obh, __nv_bfloat16* __restrict__ obl,
                            int n) {
    int wid = (blockIdx.x * blockDim.x + threadIdx.x) >> 5;
    int lane = threadIdx.x & 31;
    if (wid >= n) return;
    int v = wid;

    float c = cvec[cidx];
    float adv = adst[v];

    float a0 = lrelu(asrc[v] + adv + la[v] * c);
    int rs = ptr[v], re = ptr[v + 1];

    // pass A: exact max
    float m = a0;
    for (int e = rs + lane; e < re; e += 32)
        m = fmaxf(m, lrelu(asrc[csrc[e]] + adv + csw[e] * c));
#pragma unroll
    for (int o = 16; o; o >>= 1) m = fmaxf(m, __shfl_xor_sync(0xffffffffu, m, o));

    // pass B: fixed weights; each lane handles 4 columns (8B fp16 load per row)
    float w0 = __expf(a0 - m);
    float denp = (lane == 0) ? w0 : 0.f;
    float acc[4];
    {
        float2 raw = ((const float2*)(xl + (size_t)v * 128))[lane];
        float2 f01 = __half22float2(*(__half2*)&raw.x);
        float2 f23 = __half22float2(*(__half2*)&raw.y);
        acc[0] = w0 * f01.x; acc[1] = w0 * f01.y;
        acc[2] = w0 * f23.x; acc[3] = w0 * f23.y;
    }
    for (int b = rs; b < re; b += 32) {
        int e = b + lane;
        float w = 0.f;
        int sIdx = 0;
        if (e < re) {
            sIdx = csrc[e];
            w = __expf(lrelu(asrc[sIdx] + adv + csw[e] * c) - m);
        }
        denp += w;
        int cnt = min(32, re - b);
#pragma unroll 4
        for (int j = 0; j < cnt; j++) {
            float wj = __shfl_sync(0xffffffffu, w, j);
            int sj = __shfl_sync(0xffffffffu, sIdx, j);
            float2 raw = ((const float2*)(xl + (size_t)sj * 128))[lane];
            float2 f01 = __half22float2(*(__half2*)&raw.x);
            float2 f23 = __half22float2(*(__half2*)&raw.y);
            acc[0] += wj * f01.x; acc[1] += wj * f01.y;
            acc[2] += wj * f23.x; acc[3] += wj * f23.y;
        }
    }
#pragma unroll
    for (int o = 16; o; o >>= 1) denp += __shfl_xor_sync(0xffffffffu, denp, o);
    float inv = 1.0f / denp;

    float4 bv = ((const float4*)bias)[lane];
    float o_[4];
    o_[0] = fmaxf(acc[0] * inv + bv.x, 0.f);
    o_[1] = fmaxf(acc[1] * inv + bv.y, 0.f);
    o_[2] = fmaxf(acc[2] * inv + bv.z, 0.f);
    o_[3] = fmaxf(acc[3] * inv + bv.w, 0.f);

    __nv_bfloat16 h[4], l[4];
#pragma unroll
    for (int i = 0; i < 4; i++) {
        h[i] = __float2bfloat16(o_[i]);
        l[i] = __float2bfloat16(o_[i] - __bfloat162float(h[i]));
    }
    __nv_bfloat162* ph = (__nv_bfloat162*)(obh + (size_t)v * 128) + lane * 2;
    __nv_bfloat162* pl = (__nv_bfloat162*)(obl + (size_t)v * 128) + lane * 2;
    ph[0] = __nv_bfloat162(h[0], h[1]); ph[1] = __nv_bfloat162(h[2], h[3]);
    pl[0] = __nv_bfloat162(l[0], l[1]); pl[1] = __nv_bfloat162(l[2], l[3]);
}

// ---------------- fused mu+logstd aggregation (fp16 gather) --------------------
// xl rows are fp16 [mu cols 0-63 | logstd cols 64-127]. Lanes 0-15 apply mu
// weights, lanes 16-31 logstd weights; one gather serves both heads.
__global__ void k_aggdual(const __half* __restrict__ xl,
                          const float* __restrict__ asrcA, const float* __restrict__ adstA,
                          const float* __restrict__ asrcB, const float* __restrict__ adstB,
                          const int* __restrict__ ptr, const int* __restrict__ csrc,
                          const float* __restrict__ csw, const float* __restrict__ la,
                          const float* __restrict__ cvec,
                          const float* __restrict__ biasA, const float* __restrict__ biasB,
                          float* __restrict__ outA, float* __restrict__ outB, int n) {
    int wid = (blockIdx.x * blockDim.x + threadIdx.x) >> 5;
    int lane = threadIdx.x & 31;
    if (wid >= n) return;
    int v = wid;
    bool isA = lane < 16;

    float c = cvec[2];
    float advA = adstA[v], advB = adstB[v];
    float lav = la[v];

    float a0A = lrelu(asrcA[v] + advA + lav * c);
    float a0B = lrelu(asrcB[v] + advB);
    int rs = ptr[v], re = ptr[v + 1];

    float mA = a0A, mB = a0B;
    for (int e = rs + lane; e < re; e += 32) {
        int s = csrc[e];
        mA = fmaxf(mA, lrelu(asrcA[s] + advA + csw[e] * c));
        mB = fmaxf(mB, lrelu(asrcB[s] + advB));
    }
#pragma unroll
    for (int o = 16; o; o >>= 1) {
        mA = fmaxf(mA, __shfl_xor_sync(0xffffffffu, mA, o));
        mB = fmaxf(mB, __shfl_xor_sync(0xffffffffu, mB, o));
    }

    float w0A = __expf(a0A - mA), w0B = __expf(a0B - mB);
    float denA = (lane == 0) ? w0A : 0.f;
    float denB = (lane == 0) ? w0B : 0.f;
    float wsel0 = isA ? w0A : w0B;
    float acc[4];
    {
        float2 raw = ((const float2*)(xl + (size_t)v * 128))[lane];
        float2 f01 = __half22float2(*(__half2*)&raw.x);
        float2 f23 = __half22float2(*(__half2*)&raw.y);
        acc[0] = wsel0 * f01.x; acc[1] = wsel0 * f01.y;
        acc[2] = wsel0 * f23.x; acc[3] = wsel0 * f23.y;
    }
    for (int b = rs; b < re; b += 32) {
        int e = b + lane;
        float wA = 0.f, wB = 0.f;
        int sIdx = 0;
        if (e < re) {
            sIdx = csrc[e];
            wA = __expf(lrelu(asrcA[sIdx] + advA + csw[e] * c) - mA);
            wB = __expf(lrelu(asrcB[sIdx] + advB) - mB);
        }
        denA += wA; denB += wB;
        int cnt = min(32, re - b);
#pragma unroll 4
        for (int j = 0; j < cnt; j++) {
            float wjA = __shfl_sync(0xffffffffu, wA, j);
            float wjB = __shfl_sync(0xffffffffu, wB, j);
            int sj = __shfl_sync(0xffffffffu, sIdx, j);
            float wj = isA ? wjA : wjB;
            float2 raw = ((const float2*)(xl + (size_t)sj * 128))[lane];
            float2 f01 = __half22float2(*(__half2*)&raw.x);
            float2 f23 = __half22float2(*(__half2*)&raw.y);
            acc[0] += wj * f01.x; acc[1] += wj * f01.y;
            acc[2] += wj * f23.x; acc[3] += wj * f23.y;
        }
    }
#pragma unroll
    for (int o = 16; o; o >>= 1) {
        denA += __shfl_xor_sync(0xffffffffu, denA, o);
        denB += __shfl_xor_sync(0xffffffffu, denB, o);
    }
    float inv = isA ? (1.0f / denA) : (1.0f / denB);

    if (isA) {
        float4 bv = ((const float4*)biasA)[lane];
        ((float4*)(outA + (size_t)v * 64))[lane] =
            make_float4(acc[0] * inv + bv.x, acc[1] * inv + bv.y,
                        acc[2] * inv + bv.z, acc[3] * inv + bv.w);
    } else {
        float4 bv = ((const float4*)biasB)[lane - 16];
        ((float4*)(outB + (size_t)v * 64))[lane - 16] =
            make_float4(acc[0] * inv + bv.x, acc[1] * inv + bv.y,
                        acc[2] * inv + bv.z, acc[3] * inv + bv.w);
    }
}

// ---------------- launch ------------------------------------------------------
extern "C" void kernel_launch(void* const* d_in, const int* in_sizes, int n_in,
                              void* d_out, int out_size) {
    const float* x      = (const float*)d_in[0];
    const void*  ei_raw = d_in[1];          // int32 or int64, probed at runtime
    const float* ew     = (const float*)d_in[2];
    const float *W0 = (const float*)d_in[3],  *as0 = (const float*)d_in[4],
                *ad0 = (const float*)d_in[5], *ae0 = (const float*)d_in[6],
                *We0 = (const float*)d_in[7], *b0  = (const float*)d_in[8];
    const float *W1 = (const float*)d_in[9],  *as1 = (const float*)d_in[10],
                *ad1 = (const float*)d_in[11], *ae1 = (const float*)d_in[12],
                *We1 = (const float*)d_in[13], *b1  = (const float*)d_in[14];
    const float *Wm = (const float*)d_in[15], *asm_ = (const float*)d_in[16],
                *adm = (const float*)d_in[17], *aem = (const float*)d_in[18],
                *Wem = (const float*)d_in[19], *bm  = (const float*)d_in[20];
    const float *Wl = (const float*)d_in[21], *asl = (const float*)d_in[22],
                *adl = (const float*)d_in[23], *bl  = (const float*)d_in[24];
    float* out = (float*)d_out;

    int *p_flag, *p_cnt, *p_fill, *p_ptr, *p_bsum, *p_csrc;
    float *p_csw, *p_sumw, *p_loop, *p_xl, *p_asrc, *p_adst, *p_asrc2, *p_adst2, *p_c;
    __nv_bfloat16 *p_bh, *p_bl, *p_wh, *p_wl;
    cudaGetSymbolAddress((void**)&p_flag, g_flag64);
    cudaGetSymbolAddress((void**)&p_cnt,  g_cnt);
    cudaGetSymbolAddress((void**)&p_fill, g_fill);
    cudaGetSymbolAddress((void**)&p_ptr,  g_ptr);
    cudaGetSymbolAddress((void**)&p_bsum, g_bsum);
    cudaGetSymbolAddress((void**)&p_csrc, g_csrc);
    cudaGetSymbolAddress((void**)&p_csw,  g_csw);
    cudaGetSymbolAddress((void**)&p_sumw, g_sumw);
    cudaGetSymbolAddress((void**)&p_loop, g_loop);
    cudaGetSymbolAddress((void**)&p_xl,   g_xl);
    cudaGetSymbolAddress((void**)&p_asrc, g_asrc);
    cudaGetSymbolAddress((void**)&p_adst, g_adst);
    cudaGetSymbolAddress((void**)&p_asrc2, g_asrc2);
    cudaGetSymbolAddress((void**)&p_adst2, g_adst2);
    cudaGetSymbolAddress((void**)&p_c,    g_c);
    cudaGetSymbolAddress((void**)&p_bh,   g_bh);
    cudaGetSymbolAddress((void**)&p_bl,   g_bl);
    cudaGetSymbolAddress((void**)&p_wh,   g_wh);
    cudaGetSymbolAddress((void**)&p_wl,   g_wl);
    __half* p_xlh = (__half*)p_xl;       // fp16 alias (all layers)

    const int sm128 = 2 * (128 * 272) + 4 * (128 * 272) + 2 * 128 * 4;
    cudaFuncSetAttribute(k_mma<false>, cudaFuncAttributeMaxDynamicSharedMemorySize, sm128);
    cudaFuncSetAttribute(k_mma<true>,  cudaFuncAttributeMaxDynamicSharedMemorySize, sm128);

    const int agg_blocks = (NN + 7) / 8;     // 8 warps/block, warp per node
    const int cx_blocks  = (NN * 128 / 4 + 255) / 256;

    // 1: weight transpose + bf16 split
    k_convw<<<(49152 + 255) / 256, 256>>>(W0, W1, Wm, Wl, p_wh, p_wl);
    // 2: split input x
    k_convx<<<cx_blocks, 256>>>(x, p_bh, p_bl, NN * 128 / 4);
    // 3: zero scratch
    k_zero<<<(NN + 255) / 256, 256>>>(p_cnt, p_fill, p_sumw, NN);
    // 4: layer-0 GEMM (profiled slot) -> fp16 xl
    k_mma<false><<<MMA_GRID, 256, sm128>>>(p_bh, p_bl, p_wh, p_wl, as0, ad0,
                                           nullptr, nullptr, p_xlh,
                                           p_asrc, p_adst, nullptr, nullptr, NN, NTILES);
    // 5-9: CSR build
    k_probe<<<1, 256>>>(ei_raw, p_flag);
    k_hist<<<(NE + 511) / 512, 512>>>(ei_raw, p_flag, p_cnt, NE);
    k_scan1<<<NB_SCAN, SCAN_B>>>(p_cnt, p_ptr, p_bsum, NN);
    k_scan23<<<NB_SCAN, SCAN_B>>>(p_ptr, p_bsum, NN);
    k_scatter<<<(NE + 511) / 512, 512>>>(ei_raw, p_flag, ew, p_ptr, p_fill,
                                         p_csrc, p_csw, p_sumw, NE);
    // 10: edge-attention scalars + self-loop attrs
    k_misc<<<1 + (NN + 255) / 256, 256>>>(p_cnt, p_sumw, p_loop,
                                          We0, ae0, We1, ae1, Wem, aem, p_c, NN);

    // layer 0 aggregate (fp16 gather) -> bf16 split
    k_aggregate<<<agg_blocks, 256>>>(p_xlh, p_asrc, p_adst, p_ptr, p_csrc, p_csw,
                                     p_loop, p_c, 0, b0, p_bh, p_bl, NN);
    // layer 1
    k_mma<false><<<MMA_GRID, 256, sm128>>>(p_bh, p_bl, p_wh + 16384, p_wl + 16384, as1, ad1,
                                           nullptr, nullptr, p_xlh,
                                           p_asrc, p_adst, nullptr, nullptr, NN, NTILES);
    k_aggregate<<<agg_blocks, 256>>>(p_xlh, p_asrc, p_adst, p_ptr, p_csrc, p_csw,
                                     p_loop, p_c, 1, b1, p_bh, p_bl, NN);
    // mu+logstd fused GEMM (combined weights at offset 32768) -> fp16 xl
    k_mma<true><<<MMA_GRID, 256, sm128>>>(p_bh, p_bl, p_wh + 32768, p_wl + 32768,
                                          asm_, adm, asl, adl, p_xlh,
                                          p_asrc, p_adst, p_asrc2, p_adst2, NN, NTILES);
    // fused mu+logstd aggregation (fp16 gather)
    k_aggdual<<<agg_blocks, 256>>>(p_xlh, p_asrc, p_adst, p_asrc2, p_adst2,
                                   p_ptr, p_csrc, p_csw, p_loop, p_c,
                                   bm, bl, out, out + (size_t)NN * 64, NN);
}